// round 5
// baseline (speedup 1.0000x reference)
#include <cuda_runtime.h>
#include <cuda_bf16.h>
#include <math_constants.h>

#define NMAX 100000
#define GMAX 64
#define SLOTS 64
#define EPS 1e-5f
#define NEG_SLOPE 0.2f
#define NBLK 592          // 148 SMs x 4 blocks, all co-resident
#define NTHR 256

// ---------------- scratch (device globals; no allocation allowed) ----------------
__device__ __align__(16) float g_bufA[NMAX * 128];
__device__ __align__(16) float g_bufB[NMAX * 128];
__device__ __align__(16) unsigned g_hh[NMAX * 64];   // GAT features, bf16x2 (128 cols/node)
__device__ float g_dinv[NMAX];
__device__ int   g_deg[NMAX];
__device__ int   g_cursor[NMAX];
__device__ int   g_perm[NMAX * SLOTS];
__device__ __align__(16) float g_as[NMAX * 4];
__device__ float g_ad[NMAX * 4];
__device__ float g_pool[GMAX * 32];
__device__ float g_cnt[GMAX];
__device__ unsigned g_gen  = 0;
__device__ unsigned g_bcnt = 0;

// ---------------- grid-wide barrier ----------------
__device__ __forceinline__ void gridbar() {
    __syncthreads();
    if (threadIdx.x == 0) {
        unsigned my = atomicAdd(&g_gen, 0u);
        __threadfence();
        if (atomicAdd(&g_bcnt, 1u) == NBLK - 1u) {
            atomicExch(&g_bcnt, 0u);
            __threadfence();
            atomicAdd(&g_gen, 1u);
        } else {
            while (atomicAdd(&g_gen, 0u) == my) __nanosleep(64);
        }
        __threadfence();
    }
    __syncthreads();
}

__device__ __forceinline__ float lrelu(float x) { return x > 0.f ? x : NEG_SLOPE * x; }

__shared__ float smw[8192];

// ---------------- warp GEMM: C[n,KOUT] = A[n,KIN] @ Wsm, optional bias+BN+relu ----------------
template <int KIN, int KOUT, bool EPIL>
__device__ void stage_gemm(const float* __restrict__ A, float* __restrict__ C,
                           const float* __restrict__ W, int n, int lane, int gw, int GW,
                           const float* __restrict__ bias, const float* __restrict__ gam,
                           const float* __restrict__ bet, const float* __restrict__ mu,
                           const float* __restrict__ var) {
    constexpr int TN = KOUT / 32;
    constexpr int KW = KIN / 32;
    for (int i = threadIdx.x; i < KIN * KOUT; i += NTHR) smw[i] = W[i];
    __syncthreads();

    float Aj[TN], Bj[TN];
    if constexpr (EPIL) {
#pragma unroll
        for (int j = 0; j < TN; j++) {
            int c = lane + 32 * j;
            Aj[j] = __ldg(gam + c) * rsqrtf(__ldg(var + c) + EPS);
            Bj[j] = __ldg(bet + c) + (__ldg(bias + c) - __ldg(mu + c)) * Aj[j];
        }
    }

    for (int base = gw * 2; base < n; base += GW * 2) {
        int rows = n - base; if (rows > 2) rows = 2;
        float a[2][KW];
#pragma unroll
        for (int kk = 0; kk < KW; kk++) {
            a[0][kk] = A[(size_t)base * KIN + lane + 32 * kk];
            a[1][kk] = (rows > 1) ? A[(size_t)(base + 1) * KIN + lane + 32 * kk] : 0.f;
        }
        float acc[2][TN];
#pragma unroll
        for (int r = 0; r < 2; r++)
#pragma unroll
            for (int j = 0; j < TN; j++) acc[r][j] = 0.f;

#pragma unroll
        for (int kk = 0; kk < KW; kk++) {
            float ra0 = a[0][kk], ra1 = a[1][kk];
#pragma unroll 8
            for (int kl = 0; kl < 32; kl++) {
                float av0 = __shfl_sync(0xffffffffu, ra0, kl);
                float av1 = __shfl_sync(0xffffffffu, ra1, kl);
                const float* wrow = smw + (kk * 32 + kl) * KOUT + lane;
#pragma unroll
                for (int j = 0; j < TN; j++) {
                    float b = wrow[32 * j];
                    acc[0][j] += av0 * b;
                    acc[1][j] += av1 * b;
                }
            }
        }
#pragma unroll
        for (int r = 0; r < 2; r++) {
            if (r < rows) {
#pragma unroll
                for (int j = 0; j < TN; j++) {
                    float v = acc[r][j];
                    if constexpr (EPIL) v = fmaxf(v * Aj[j] + Bj[j], 0.f);
                    C[(size_t)(base + r) * KOUT + lane + 32 * j] = v;
                }
            }
        }
    }
}

// ---------------- GCN aggregation: warp per node, 8-wide unrolled gather ----------------
template <int D, bool EPIL>
__device__ void stage_agg(const float* __restrict__ feat, float* __restrict__ out, int n,
                          int lane, int gw, int GW,
                          const float* __restrict__ bias, const float* __restrict__ gam,
                          const float* __restrict__ bet, const float* __restrict__ mu,
                          const float* __restrict__ var) {
    constexpr int V = D / 32;
    float Aj[V], Bj[V];
    if constexpr (EPIL) {
#pragma unroll
        for (int j = 0; j < V; j++) {
            int d = lane * V + j;
            Aj[j] = __ldg(gam + d) * rsqrtf(__ldg(var + d) + EPS);
            Bj[j] = __ldg(bet + d) + (__ldg(bias + d) - __ldg(mu + d)) * Aj[j];
        }
    }
    for (int w = gw; w < n; w += GW) {
        float di = g_dinv[w];
        int cnt = g_deg[w];
        const int* __restrict__ pl = g_perm + (size_t)w * SLOTS;
        float acc[V];
        {
            float nm = di * di;
            const float* row = feat + (size_t)w * D + lane * V;
#pragma unroll
            for (int j = 0; j < V; j++) acc[j] = nm * __ldg(row + j);
        }
        int e = 0;
        for (; e + 8 <= cnt; e += 8) {
            int s[8]; float nm[8];
#pragma unroll
            for (int u = 0; u < 8; u++) s[u] = __ldg(pl + e + u);
#pragma unroll
            for (int u = 0; u < 8; u++) nm[u] = di * __ldg(g_dinv + s[u]);
            if constexpr (V == 2) {
                float2 v[8];
#pragma unroll
                for (int u = 0; u < 8; u++)
                    v[u] = __ldg(reinterpret_cast<const float2*>(feat + (size_t)s[u] * D) + lane);
#pragma unroll
                for (int u = 0; u < 8; u++) { acc[0] += nm[u] * v[u].x; acc[1] += nm[u] * v[u].y; }
            } else {
                float v[8];
#pragma unroll
                for (int u = 0; u < 8; u++) v[u] = __ldg(feat + (size_t)s[u] * D + lane);
#pragma unroll
                for (int u = 0; u < 8; u++) acc[0] += nm[u] * v[u];
            }
        }
        for (; e + 4 <= cnt; e += 4) {
            int s[4]; float nm[4];
#pragma unroll
            for (int u = 0; u < 4; u++) s[u] = __ldg(pl + e + u);
#pragma unroll
            for (int u = 0; u < 4; u++) nm[u] = di * __ldg(g_dinv + s[u]);
            if constexpr (V == 2) {
                float2 v[4];
#pragma unroll
                for (int u = 0; u < 4; u++)
                    v[u] = __ldg(reinterpret_cast<const float2*>(feat + (size_t)s[u] * D) + lane);
#pragma unroll
                for (int u = 0; u < 4; u++) { acc[0] += nm[u] * v[u].x; acc[1] += nm[u] * v[u].y; }
            } else {
                float v[4];
#pragma unroll
                for (int u = 0; u < 4; u++) v[u] = __ldg(feat + (size_t)s[u] * D + lane);
#pragma unroll
                for (int u = 0; u < 4; u++) acc[0] += nm[u] * v[u];
            }
        }
        for (; e < cnt; e++) {
            int sn = __ldg(pl + e);
            float nm = di * __ldg(g_dinv + sn);
            if constexpr (V == 2) {
                float2 v = __ldg(reinterpret_cast<const float2*>(feat + (size_t)sn * D) + lane);
                acc[0] += nm * v.x; acc[1] += nm * v.y;
            } else {
                acc[0] += nm * __ldg(feat + (size_t)sn * D + lane);
            }
        }
        if constexpr (EPIL) {
#pragma unroll
            for (int j = 0; j < V; j++) acc[j] = fmaxf(acc[j] * Aj[j] + Bj[j], 0.f);
        }
        float* orow = out + (size_t)w * D + lane * V;
        if constexpr (V == 2) *reinterpret_cast<float2*>(orow) = make_float2(acc[0], acc[1]);
        else orow[0] = acc[0];
    }
}

__device__ __forceinline__ float2 bf2f(unsigned u) {
    return __bfloat1622float2(*reinterpret_cast<const __nv_bfloat162*>(&u));
}

// ---------------- the megakernel ----------------
__global__ void __launch_bounds__(NTHR, 4)
k_mega(const float* __restrict__ x, const int* __restrict__ src, const int* __restrict__ dst,
       const int* __restrict__ batch, int n, int E, int G,
       const float* W1, const float* b1, const float* g1, const float* be1, const float* m1, const float* v1,
       const float* W2, const float* b2, const float* g2, const float* be2, const float* m2, const float* v2,
       const float* W3, const float* b3, const float* g3, const float* be3, const float* m3, const float* v3,
       const float* Wg, const float* ags, const float* agd, const float* bg,
       const float* Wc1, const float* bc1, const float* Wc2, const float* bc2,
       float* __restrict__ out) {
    int tid = threadIdx.x;
    int lane = tid & 31;
    int gt = blockIdx.x * NTHR + tid;
    int gw = gt >> 5;
    const int GT = NBLK * NTHR;
    const int GW = GT / 32;

    // S0: zero cursors, pool, cnt
    for (int i = gt; i < n; i += GT) g_cursor[i] = 0;
    if (gt < GMAX * 32) g_pool[gt] = 0.f;
    if (gt < GMAX) g_cnt[gt] = 0.f;
    gridbar();

    // S1: bucket scatter by dst
    for (int e = gt; e < E; e += GT) {
        int d = dst[e];
        int slot = atomicAdd(&g_cursor[d], 1);
        if (slot < SLOTS) g_perm[(size_t)d * SLOTS + slot] = src[e];
    }
    gridbar();

    // S2: finalize degree / dinv
    for (int i = gt; i < n; i += GT) {
        int c = g_cursor[i];
        if (c > SLOTS) c = SLOTS;
        g_deg[i] = c;
        g_dinv[i] = rsqrtf((float)(c + 1));
    }
    gridbar();

    // S3: aggregate raw input (linearity)
    stage_agg<64, false>(x, g_bufA, n, lane, gw, GW, nullptr, nullptr, nullptr, nullptr, nullptr);
    gridbar();

    // S4: GEMM 64->128 + bias/BN/relu
    stage_gemm<64, 128, true>(g_bufA, g_bufB, W1, n, lane, gw, GW, b1, g1, be1, m1, v1);
    gridbar();

    // S5: GEMM 128->64
    stage_gemm<128, 64, false>(g_bufB, g_bufA, W2, n, lane, gw, GW, nullptr, nullptr, nullptr, nullptr, nullptr);
    gridbar();

    // S6: aggregate + bias/BN/relu
    stage_agg<64, true>(g_bufA, g_bufB, n, lane, gw, GW, b2, g2, be2, m2, v2);
    gridbar();

    // S7: GEMM 64->32
    stage_gemm<64, 32, false>(g_bufB, g_bufA, W3, n, lane, gw, GW, nullptr, nullptr, nullptr, nullptr, nullptr);
    gridbar();

    // S8: aggregate + bias/BN/relu
    stage_agg<32, true>(g_bufA, g_bufB, n, lane, gw, GW, b3, g3, be3, m3, v3);
    gridbar();

    // S9: GAT projection 32->128 (4 heads x 32)
    stage_gemm<32, 128, false>(g_bufB, g_bufA, Wg, n, lane, gw, GW, nullptr, nullptr, nullptr, nullptr, nullptr);
    gridbar();

    // S10: attention coefficients + bf16 copy of hh
    for (int i = tid; i < 128; i += NTHR) { smw[i] = ags[i]; smw[128 + i] = agd[i]; }
    __syncthreads();
    for (int t = gt; t < n * 4; t += GT) {
        int node = t >> 2, h = t & 3;
        const float* row = g_bufA + (size_t)node * 128 + h * 32;
        float s = 0.f, d = 0.f;
        unsigned* hrow = g_hh + (size_t)node * 64 + h * 16;
#pragma unroll
        for (int k = 0; k < 16; k++) {
            float x0 = __ldg(row + 2 * k);
            float x1 = __ldg(row + 2 * k + 1);
            s += x0 * smw[h * 32 + 2 * k] + x1 * smw[h * 32 + 2 * k + 1];
            d += x0 * smw[128 + h * 32 + 2 * k] + x1 * smw[128 + h * 32 + 2 * k + 1];
            __nv_bfloat162 p = __floats2bfloat162_rn(x0, x1);
            hrow[k] = *reinterpret_cast<unsigned*>(&p);
        }
        g_as[t] = s;
        g_ad[t] = d;
    }
    gridbar();

    // S11: GAT aggregation (bf16 gather, 4-wide unroll) + bias/relu + fused pool
    {
        const uint2* hb = reinterpret_cast<const uint2*>(g_hh);
        int myh = lane >> 3;
        for (int nId = gw; nId < n; nId += GW) {
            const int* __restrict__ pl = g_perm + (size_t)nId * SLOTS;
            int cnt = g_deg[nId];
            float adn0 = __ldg(&g_ad[nId * 4 + 0]);
            float adn1 = __ldg(&g_ad[nId * 4 + 1]);
            float adn2 = __ldg(&g_ad[nId * 4 + 2]);
            float adn3 = __ldg(&g_ad[nId * 4 + 3]);

            // pass 1: raw max per head (lrelu deferred — monotone)
            float m0 = -CUDART_INF_F, m1_ = -CUDART_INF_F, m2_ = -CUDART_INF_F, m3_ = -CUDART_INF_F;
            for (int e = lane; e <= cnt; e += 32) {
                int sn = (e < cnt) ? __ldg(pl + e) : nId;
                float4 v = __ldg(reinterpret_cast<const float4*>(g_as) + sn);
                m0  = fmaxf(m0,  v.x + adn0);
                m1_ = fmaxf(m1_, v.y + adn1);
                m2_ = fmaxf(m2_, v.z + adn2);
                m3_ = fmaxf(m3_, v.w + adn3);
            }
#pragma unroll
            for (int off = 16; off; off >>= 1) {
                m0  = fmaxf(m0,  __shfl_xor_sync(0xffffffffu, m0, off));
                m1_ = fmaxf(m1_, __shfl_xor_sync(0xffffffffu, m1_, off));
                m2_ = fmaxf(m2_, __shfl_xor_sync(0xffffffffu, m2_, off));
                m3_ = fmaxf(m3_, __shfl_xor_sync(0xffffffffu, m3_, off));
            }
            float mx  = lrelu((myh == 0) ? m0 : (myh == 1) ? m1_ : (myh == 2) ? m2_ : m3_);
            float adn = (myh == 0) ? adn0 : (myh == 1) ? adn1 : (myh == 2) ? adn2 : adn3;

            // pass 2: 4-wide unrolled weighted aggregation
            float4 acc = make_float4(0.f, 0.f, 0.f, 0.f);
            float den = 0.f;
            int e = 0;
            for (; e + 4 <= cnt; e += 4) {
                int s0 = __ldg(pl + e + 0), s1 = __ldg(pl + e + 1);
                int s2 = __ldg(pl + e + 2), s3 = __ldg(pl + e + 3);
                uint2 r0 = __ldg(hb + (size_t)s0 * 32 + lane);
                uint2 r1 = __ldg(hb + (size_t)s1 * 32 + lane);
                uint2 r2 = __ldg(hb + (size_t)s2 * 32 + lane);
                uint2 r3 = __ldg(hb + (size_t)s3 * 32 + lane);
                float w0 = __expf(lrelu(__ldg(&g_as[s0 * 4 + myh]) + adn) - mx);
                float w1 = __expf(lrelu(__ldg(&g_as[s1 * 4 + myh]) + adn) - mx);
                float w2 = __expf(lrelu(__ldg(&g_as[s2 * 4 + myh]) + adn) - mx);
                float w3 = __expf(lrelu(__ldg(&g_as[s3 * 4 + myh]) + adn) - mx);
                den += (w0 + w1) + (w2 + w3);
                float2 a0 = bf2f(r0.x), b0 = bf2f(r0.y);
                float2 a1 = bf2f(r1.x), b1 = bf2f(r1.y);
                float2 a2 = bf2f(r2.x), b2 = bf2f(r2.y);
                float2 a3 = bf2f(r3.x), b3 = bf2f(r3.y);
                acc.x += w0 * a0.x + w1 * a1.x + w2 * a2.x + w3 * a3.x;
                acc.y += w0 * a0.y + w1 * a1.y + w2 * a2.y + w3 * a3.y;
                acc.z += w0 * b0.x + w1 * b1.x + w2 * b2.x + w3 * b3.x;
                acc.w += w0 * b0.y + w1 * b1.y + w2 * b2.y + w3 * b3.y;
            }
            for (; e <= cnt; e++) {
                int sn = (e < cnt) ? __ldg(pl + e) : nId;
                float w = __expf(lrelu(__ldg(&g_as[sn * 4 + myh]) + adn) - mx);
                den += w;
                uint2 r = __ldg(hb + (size_t)sn * 32 + lane);
                float2 a = bf2f(r.x), b = bf2f(r.y);
                acc.x += w * a.x; acc.y += w * a.y; acc.z += w * b.x; acc.w += w * b.y;
            }
            float inv = 1.f / den;
            acc.x *= inv; acc.y *= inv; acc.z *= inv; acc.w *= inv;
#pragma unroll
            for (int off = 8; off <= 16; off <<= 1) {
                acc.x += __shfl_xor_sync(0xffffffffu, acc.x, off);
                acc.y += __shfl_xor_sync(0xffffffffu, acc.y, off);
                acc.z += __shfl_xor_sync(0xffffffffu, acc.z, off);
                acc.w += __shfl_xor_sync(0xffffffffu, acc.w, off);
            }
            if (lane < 8) {
                float4 bgv = __ldg(reinterpret_cast<const float4*>(bg) + lane);
                int b = __ldg(batch + nId);
                float* p = &g_pool[b * 32 + lane * 4];
                atomicAdd(p + 0, fmaxf(acc.x * 0.25f + bgv.x, 0.f));
                atomicAdd(p + 1, fmaxf(acc.y * 0.25f + bgv.y, 0.f));
                atomicAdd(p + 2, fmaxf(acc.z * 0.25f + bgv.z, 0.f));
                atomicAdd(p + 3, fmaxf(acc.w * 0.25f + bgv.w, 0.f));
                if (lane == 0) atomicAdd(&g_cnt[b], 1.f);
            }
        }
    }
    gridbar();

    // S12: classifier head (block 0 only)
    if (blockIdx.x == 0) {
        float* pooled = smw;
        float* hid = smw + GMAX * 32;
        for (int t = tid; t < G * 32; t += NTHR) pooled[t] = g_pool[t] / fmaxf(g_cnt[t >> 5], 1.f);
        __syncthreads();
        for (int t = tid; t < G * 16; t += NTHR) {
            int g = t >> 4, j = t & 15;
            float s = __ldg(bc1 + j);
            for (int k = 0; k < 32; k++) s += pooled[g * 32 + k] * __ldg(Wc1 + k * 16 + j);
            hid[t] = fmaxf(s, 0.f);
        }
        __syncthreads();
        for (int t = tid; t < G * 5; t += NTHR) {
            int g = t / 5, c = t % 5;
            float s = __ldg(bc2 + c);
            for (int k = 0; k < 16; k++) s += hid[g * 16 + k] * __ldg(Wc2 + k * 5 + c);
            out[t] = s;
        }
    }
}

// ---------------- host ----------------
extern "C" void kernel_launch(void* const* d_in, const int* in_sizes, int n_in,
                              void* d_out, int out_size) {
    const float* x = (const float*)d_in[0];
    const int* ei = (const int*)d_in[1];
    const int* batch = (const int*)d_in[2];
    int n = in_sizes[0] / 64;
    int E = in_sizes[1] / 2;
    int G = out_size / 5;

    const float *W1, *b1, *W2, *b2, *W3, *b3;
    const float *g1, *be1, *m1, *v1, *g2, *be2, *m2, *v2, *g3, *be3, *m3, *v3;
    const float *Wg, *ags, *agd, *bg, *Wc1, *bc1, *Wc2, *bc2;

    if (in_sizes[5] == 128 * 64) {
        W1 = (const float*)d_in[3];  b1 = (const float*)d_in[4];
        W2 = (const float*)d_in[5];  b2 = (const float*)d_in[6];
        W3 = (const float*)d_in[7];  b3 = (const float*)d_in[8];
        g1 = (const float*)d_in[9];  be1 = (const float*)d_in[10];
        m1 = (const float*)d_in[11]; v1 = (const float*)d_in[12];
        g2 = (const float*)d_in[13]; be2 = (const float*)d_in[14];
        m2 = (const float*)d_in[15]; v2 = (const float*)d_in[16];
        g3 = (const float*)d_in[17]; be3 = (const float*)d_in[18];
        m3 = (const float*)d_in[19]; v3 = (const float*)d_in[20];
        Wg = (const float*)d_in[21]; ags = (const float*)d_in[22];
        agd = (const float*)d_in[23]; bg = (const float*)d_in[24];
        Wc1 = (const float*)d_in[25]; bc1 = (const float*)d_in[26];
        Wc2 = (const float*)d_in[27]; bc2 = (const float*)d_in[28];
    } else {
        W1 = (const float*)d_in[3];  b1 = (const float*)d_in[4];
        g1 = (const float*)d_in[5];  be1 = (const float*)d_in[6];
        m1 = (const float*)d_in[7];  v1 = (const float*)d_in[8];
        W2 = (const float*)d_in[9];  b2 = (const float*)d_in[10];
        g2 = (const float*)d_in[11]; be2 = (const float*)d_in[12];
        m2 = (const float*)d_in[13]; v2 = (const float*)d_in[14];
        W3 = (const float*)d_in[15]; b3 = (const float*)d_in[16];
        g3 = (const float*)d_in[17]; be3 = (const float*)d_in[18];
        m3 = (const float*)d_in[19]; v3 = (const float*)d_in[20];
        Wg = (const float*)d_in[21]; ags = (const float*)d_in[22];
        agd = (const float*)d_in[23]; bg = (const float*)d_in[24];
        Wc1 = (const float*)d_in[25]; bc1 = (const float*)d_in[26];
        Wc2 = (const float*)d_in[27]; bc2 = (const float*)d_in[28];
    }

    const int* src = ei;
    const int* dst = ei + E;

    k_mega<<<NBLK, NTHR>>>(x, src, dst, batch, n, E, G,
                           W1, b1, g1, be1, m1, v1,
                           W2, b2, g2, be2, m2, v2,
                           W3, b3, g3, be3, m3, v3,
                           Wg, ags, agd, bg,
                           Wc1, bc1, Wc2, bc2,
                           (float*)d_out);
}

// round 6
// speedup vs baseline: 1.0358x; 1.0358x over previous
#include <cuda_runtime.h>
#include <cuda_bf16.h>
#include <math_constants.h>

#define NMAX 100000
#define GMAX 64
#define SLOTS 64
#define EPS 1e-5f
#define NEG_SLOPE 0.2f
#define NBLK 592          // 148 SMs x 4 blocks, all co-resident
#define NTHR 256

// ---------------- scratch (device globals) ----------------
__device__ __align__(16) float g_bufA[NMAX * 128];
__device__ __align__(16) float g_bufB[NMAX * 128];
__device__ __align__(16) unsigned g_hh[NMAX * 64];   // bf16x2 buffer (up to 128 cols/node)
__device__ __align__(16) unsigned g_xbf[NMAX * 32];  // bf16x2 buffer (up to 64 cols/node)
__device__ float g_dinv[NMAX];
__device__ int   g_deg[NMAX];
__device__ int   g_cursor[NMAX];
__device__ int   g_perm[NMAX * SLOTS];
__device__ __align__(16) float g_as[NMAX * 4];
__device__ float g_ad[NMAX * 4];
__device__ float g_pool[GMAX * 32];
__device__ float g_cnt[GMAX];
__device__ unsigned g_gen  = 0;
__device__ unsigned g_bcnt = 0;

// ---------------- grid-wide barrier ----------------
__device__ __forceinline__ void gridbar() {
    __syncthreads();
    if (threadIdx.x == 0) {
        unsigned my = atomicAdd(&g_gen, 0u);
        __threadfence();
        if (atomicAdd(&g_bcnt, 1u) == NBLK - 1u) {
            atomicExch(&g_bcnt, 0u);
            __threadfence();
            atomicAdd(&g_gen, 1u);
        } else {
            while (atomicAdd(&g_gen, 0u) == my) __nanosleep(64);
        }
        __threadfence();
    }
    __syncthreads();
}

__device__ __forceinline__ float lrelu(float x) { return x > 0.f ? x : NEG_SLOPE * x; }
__device__ __forceinline__ float2 bf2f(unsigned u) {
    return __bfloat1622float2(*reinterpret_cast<const __nv_bfloat162*>(&u));
}
__device__ __forceinline__ unsigned f2bf(float a, float b) {
    __nv_bfloat162 p = __floats2bfloat162_rn(a, b);
    return *reinterpret_cast<unsigned*>(&p);
}

__shared__ __align__(16) float smw[8192];

// ---------------- GEMM fp32-out: transposed W, col = lane + 32j, TN=4 (KOUT=128) ----------------
template <int KIN, bool EPIL>
__device__ void stage_gemm_f128(const float* __restrict__ A, float* __restrict__ C,
                                const float* __restrict__ W, int n, int lane, int gw, int GW,
                                const float* __restrict__ bias, const float* __restrict__ gam,
                                const float* __restrict__ bet, const float* __restrict__ mu,
                                const float* __restrict__ var) {
    constexpr int KOUT = 128;
    constexpr int TN = 4;
    constexpr int KW = KIN / 32;
    for (int idx = threadIdx.x; idx < KIN * KOUT; idx += NTHR) {
        int r = idx / KOUT, c = idx % KOUT;
        smw[r * KOUT + (c & 31) * TN + (c >> 5)] = W[idx];
    }
    __syncthreads();

    float Aj[TN], Bj[TN];
    if constexpr (EPIL) {
#pragma unroll
        for (int j = 0; j < TN; j++) {
            int c = lane + 32 * j;
            Aj[j] = __ldg(gam + c) * rsqrtf(__ldg(var + c) + EPS);
            Bj[j] = __ldg(bet + c) + (__ldg(bias + c) - __ldg(mu + c)) * Aj[j];
        }
    }

    for (int base = gw * 2; base < n; base += GW * 2) {
        int rows = n - base; if (rows > 2) rows = 2;
        float a[2][KW];
#pragma unroll
        for (int kk = 0; kk < KW; kk++) {
            a[0][kk] = A[(size_t)base * KIN + lane + 32 * kk];
            a[1][kk] = (rows > 1) ? A[(size_t)(base + 1) * KIN + lane + 32 * kk] : 0.f;
        }
        float acc[2][TN];
#pragma unroll
        for (int r = 0; r < 2; r++)
#pragma unroll
            for (int j = 0; j < TN; j++) acc[r][j] = 0.f;

#pragma unroll
        for (int kk = 0; kk < KW; kk++) {
            float ra0 = a[0][kk], ra1 = a[1][kk];
#pragma unroll 8
            for (int kl = 0; kl < 32; kl++) {
                float av0 = __shfl_sync(0xffffffffu, ra0, kl);
                float av1 = __shfl_sync(0xffffffffu, ra1, kl);
                float4 b4 = *reinterpret_cast<const float4*>(smw + (kk * 32 + kl) * KOUT + lane * 4);
                acc[0][0] += av0 * b4.x; acc[0][1] += av0 * b4.y;
                acc[0][2] += av0 * b4.z; acc[0][3] += av0 * b4.w;
                acc[1][0] += av1 * b4.x; acc[1][1] += av1 * b4.y;
                acc[1][2] += av1 * b4.z; acc[1][3] += av1 * b4.w;
            }
        }
#pragma unroll
        for (int r = 0; r < 2; r++) {
            if (r < rows) {
#pragma unroll
                for (int j = 0; j < TN; j++) {
                    float v = acc[r][j];
                    if constexpr (EPIL) v = fmaxf(v * Aj[j] + Bj[j], 0.f);
                    C[(size_t)(base + r) * KOUT + lane + 32 * j] = v;
                }
            }
        }
    }
}

// ---------------- GEMM bf16-out, KOUT=64: paired cols (2*lane, 2*lane+1) ----------------
template <int KIN>
__device__ void stage_gemm_b64(const float* __restrict__ A, unsigned* __restrict__ Cb,
                               const float* __restrict__ W, int n, int lane, int gw, int GW) {
    constexpr int KOUT = 64;
    constexpr int KW = KIN / 32;
    for (int idx = threadIdx.x; idx < KIN * KOUT; idx += NTHR) smw[idx] = W[idx];
    __syncthreads();

    for (int base = gw * 2; base < n; base += GW * 2) {
        int rows = n - base; if (rows > 2) rows = 2;
        float a[2][KW];
#pragma unroll
        for (int kk = 0; kk < KW; kk++) {
            a[0][kk] = A[(size_t)base * KIN + lane + 32 * kk];
            a[1][kk] = (rows > 1) ? A[(size_t)(base + 1) * KIN + lane + 32 * kk] : 0.f;
        }
        float a00 = 0.f, a01 = 0.f, a10 = 0.f, a11 = 0.f;
#pragma unroll
        for (int kk = 0; kk < KW; kk++) {
            float ra0 = a[0][kk], ra1 = a[1][kk];
#pragma unroll 8
            for (int kl = 0; kl < 32; kl++) {
                float av0 = __shfl_sync(0xffffffffu, ra0, kl);
                float av1 = __shfl_sync(0xffffffffu, ra1, kl);
                float2 b2 = *reinterpret_cast<const float2*>(smw + (kk * 32 + kl) * KOUT + 2 * lane);
                a00 += av0 * b2.x; a01 += av0 * b2.y;
                a10 += av1 * b2.x; a11 += av1 * b2.y;
            }
        }
        Cb[(size_t)base * 32 + lane] = f2bf(a00, a01);
        if (rows > 1) Cb[(size_t)(base + 1) * 32 + lane] = f2bf(a10, a11);
    }
}

// ---------------- GEMM bf16-out, KOUT=32: col = lane, shfl-pack pairs ----------------
template <int KIN>
__device__ void stage_gemm_b32(const float* __restrict__ A, unsigned* __restrict__ Cb,
                               const float* __restrict__ W, int n, int lane, int gw, int GW) {
    constexpr int KOUT = 32;
    constexpr int KW = KIN / 32;
    for (int idx = threadIdx.x; idx < KIN * KOUT; idx += NTHR) smw[idx] = W[idx];
    __syncthreads();

    for (int base = gw * 2; base < n; base += GW * 2) {
        int rows = n - base; if (rows > 2) rows = 2;
        float a[2][KW];
#pragma unroll
        for (int kk = 0; kk < KW; kk++) {
            a[0][kk] = A[(size_t)base * KIN + lane + 32 * kk];
            a[1][kk] = (rows > 1) ? A[(size_t)(base + 1) * KIN + lane + 32 * kk] : 0.f;
        }
        float c0 = 0.f, c1 = 0.f;
#pragma unroll
        for (int kk = 0; kk < KW; kk++) {
            float ra0 = a[0][kk], ra1 = a[1][kk];
#pragma unroll 8
            for (int kl = 0; kl < 32; kl++) {
                float av0 = __shfl_sync(0xffffffffu, ra0, kl);
                float av1 = __shfl_sync(0xffffffffu, ra1, kl);
                float b = smw[(kk * 32 + kl) * KOUT + lane];
                c0 += av0 * b; c1 += av1 * b;
            }
        }
        float o0 = __shfl_down_sync(0xffffffffu, c0, 1);
        float o1 = __shfl_down_sync(0xffffffffu, c1, 1);
        if (!(lane & 1)) {
            Cb[(size_t)base * 16 + (lane >> 1)] = f2bf(c0, o0);
            if (rows > 1) Cb[(size_t)(base + 1) * 16 + (lane >> 1)] = f2bf(c1, o1);
        }
    }
}

// ---------------- GCN aggregation from bf16 features, fp32 accumulate/output ----------------
template <int D, bool EPIL>
__device__ void stage_agg_bf(const unsigned* __restrict__ featb, float* __restrict__ out, int n,
                             int lane, int gw, int GW,
                             const float* __restrict__ bias, const float* __restrict__ gam,
                             const float* __restrict__ bet, const float* __restrict__ mu,
                             const float* __restrict__ var) {
    constexpr int PR = D / 2;                 // uints per row
    int li = lane & (PR - 1);                 // PR is 16 or 32 (power of 2)
    float A0 = 1.f, A1 = 1.f, B0 = 0.f, B1 = 0.f;
    if constexpr (EPIL) {
        int d0 = 2 * li, d1 = 2 * li + 1;
        A0 = __ldg(gam + d0) * rsqrtf(__ldg(var + d0) + EPS);
        B0 = __ldg(bet + d0) + (__ldg(bias + d0) - __ldg(mu + d0)) * A0;
        A1 = __ldg(gam + d1) * rsqrtf(__ldg(var + d1) + EPS);
        B1 = __ldg(bet + d1) + (__ldg(bias + d1) - __ldg(mu + d1)) * A1;
    }
    for (int w = gw; w < n; w += GW) {
        float di = g_dinv[w];
        int cnt = g_deg[w];
        const int* __restrict__ pl = g_perm + (size_t)w * SLOTS;
        float ax, ay;
        {
            float nm = di * di;
            float2 v = bf2f(__ldg(featb + (size_t)w * PR + li));
            ax = nm * v.x; ay = nm * v.y;
        }
        int e = 0;
        for (; e + 8 <= cnt; e += 8) {
            int s[8]; float nm[8]; unsigned r[8];
#pragma unroll
            for (int u = 0; u < 8; u++) s[u] = __ldg(pl + e + u);
#pragma unroll
            for (int u = 0; u < 8; u++) r[u] = __ldg(featb + (size_t)s[u] * PR + li);
#pragma unroll
            for (int u = 0; u < 8; u++) nm[u] = di * __ldg(g_dinv + s[u]);
#pragma unroll
            for (int u = 0; u < 8; u++) {
                float2 v = bf2f(r[u]);
                ax += nm[u] * v.x; ay += nm[u] * v.y;
            }
        }
        for (; e + 4 <= cnt; e += 4) {
            int s[4]; float nm[4]; unsigned r[4];
#pragma unroll
            for (int u = 0; u < 4; u++) s[u] = __ldg(pl + e + u);
#pragma unroll
            for (int u = 0; u < 4; u++) r[u] = __ldg(featb + (size_t)s[u] * PR + li);
#pragma unroll
            for (int u = 0; u < 4; u++) nm[u] = di * __ldg(g_dinv + s[u]);
#pragma unroll
            for (int u = 0; u < 4; u++) {
                float2 v = bf2f(r[u]);
                ax += nm[u] * v.x; ay += nm[u] * v.y;
            }
        }
        for (; e < cnt; e++) {
            int sn = __ldg(pl + e);
            float nm = di * __ldg(g_dinv + sn);
            float2 v = bf2f(__ldg(featb + (size_t)sn * PR + li));
            ax += nm * v.x; ay += nm * v.y;
        }
        if constexpr (EPIL) {
            ax = fmaxf(ax * A0 + B0, 0.f);
            ay = fmaxf(ay * A1 + B1, 0.f);
        }
        if (lane < PR)
            *reinterpret_cast<float2*>(out + (size_t)w * D + li * 2) = make_float2(ax, ay);
    }
}

// ---------------- the megakernel ----------------
__global__ void __launch_bounds__(NTHR, 4)
k_mega(const float* __restrict__ x, const int* __restrict__ src, const int* __restrict__ dst,
       const int* __restrict__ batch, int n, int E, int G,
       const float* W1, const float* b1, const float* g1, const float* be1, const float* m1, const float* v1,
       const float* W2, const float* b2, const float* g2, const float* be2, const float* m2, const float* v2,
       const float* W3, const float* b3, const float* g3, const float* be3, const float* m3, const float* v3,
       const float* Wg, const float* ags, const float* agd, const float* bg,
       const float* Wc1, const float* bc1, const float* Wc2, const float* bc2,
       float* __restrict__ out) {
    int tid = threadIdx.x;
    int lane = tid & 31;
    int gt = blockIdx.x * NTHR + tid;
    int gw = gt >> 5;
    const int GT = NBLK * NTHR;
    const int GW = GT / 32;

    // S0: zero cursors/pool/cnt + convert x -> bf16
    for (int i = gt; i < n; i += GT) g_cursor[i] = 0;
    if (gt < GMAX * 32) g_pool[gt] = 0.f;
    if (gt < GMAX) g_cnt[gt] = 0.f;
    for (int i = gt; i < n * 32; i += GT)
        g_xbf[i] = f2bf(__ldg(x + 2 * i), __ldg(x + 2 * i + 1));
    gridbar();

    // S1: bucket scatter by dst
    for (int e = gt; e < E; e += GT) {
        int d = dst[e];
        int slot = atomicAdd(&g_cursor[d], 1);
        if (slot < SLOTS) g_perm[(size_t)d * SLOTS + slot] = src[e];
    }
    gridbar();

    // S2: finalize degree / dinv
    for (int i = gt; i < n; i += GT) {
        int c = g_cursor[i];
        if (c > SLOTS) c = SLOTS;
        g_deg[i] = c;
        g_dinv[i] = rsqrtf((float)(c + 1));
    }
    gridbar();

    // S3: aggregate bf16 input (linearity)
    stage_agg_bf<64, false>(g_xbf, g_bufA, n, lane, gw, GW, nullptr, nullptr, nullptr, nullptr, nullptr);
    gridbar();

    // S4: GEMM 64->128 + bias/BN/relu (fp32 out)
    stage_gemm_f128<64, true>(g_bufA, g_bufB, W1, n, lane, gw, GW, b1, g1, be1, m1, v1);
    gridbar();

    // S5: GEMM 128->64, bf16 out
    stage_gemm_b64<128>(g_bufB, g_hh, W2, n, lane, gw, GW);
    gridbar();

    // S6: aggregate bf16 + bias/BN/relu (fp32 out)
    stage_agg_bf<64, true>(g_hh, g_bufA, n, lane, gw, GW, b2, g2, be2, m2, v2);
    gridbar();

    // S7: GEMM 64->32, bf16 out
    stage_gemm_b32<64>(g_bufA, g_xbf, W3, n, lane, gw, GW);
    gridbar();

    // S8: aggregate bf16 + bias/BN/relu (fp32 out, 32-dim)
    stage_agg_bf<32, true>(g_xbf, g_bufB, n, lane, gw, GW, b3, g3, be3, m3, v3);
    gridbar();

    // S9: GAT projection 32->128 (fp32 out)
    stage_gemm_f128<32, false>(g_bufB, g_bufA, Wg, n, lane, gw, GW, nullptr, nullptr, nullptr, nullptr, nullptr);
    gridbar();

    // S10: attention coefficients + bf16 copy of hh
    for (int i = tid; i < 128; i += NTHR) { smw[i] = ags[i]; smw[128 + i] = agd[i]; }
    __syncthreads();
    for (int t = gt; t < n * 4; t += GT) {
        int node = t >> 2, h = t & 3;
        const float* row = g_bufA + (size_t)node * 128 + h * 32;
        float s = 0.f, d = 0.f;
        unsigned* hrow = g_hh + (size_t)node * 64 + h * 16;
#pragma unroll
        for (int k = 0; k < 16; k++) {
            float x0 = __ldg(row + 2 * k);
            float x1 = __ldg(row + 2 * k + 1);
            s += x0 * smw[h * 32 + 2 * k] + x1 * smw[h * 32 + 2 * k + 1];
            d += x0 * smw[128 + h * 32 + 2 * k] + x1 * smw[128 + h * 32 + 2 * k + 1];
            hrow[k] = f2bf(x0, x1);
        }
        g_as[t] = s;
        g_ad[t] = d;
    }
    gridbar();

    // S11: GAT aggregation (bf16 gather) + bias/relu + fused pool
    {
        const uint2* hb = reinterpret_cast<const uint2*>(g_hh);
        int myh = lane >> 3;
        for (int nId = gw; nId < n; nId += GW) {
            const int* __restrict__ pl = g_perm + (size_t)nId * SLOTS;
            int cnt = g_deg[nId];
            float adn0 = __ldg(&g_ad[nId * 4 + 0]);
            float adn1 = __ldg(&g_ad[nId * 4 + 1]);
            float adn2 = __ldg(&g_ad[nId * 4 + 2]);
            float adn3 = __ldg(&g_ad[nId * 4 + 3]);

            float m0 = -CUDART_INF_F, m1_ = -CUDART_INF_F, m2_ = -CUDART_INF_F, m3_ = -CUDART_INF_F;
            for (int e = lane; e <= cnt; e += 32) {
                int sn = (e < cnt) ? __ldg(pl + e) : nId;
                float4 v = __ldg(reinterpret_cast<const float4*>(g_as) + sn);
                m0  = fmaxf(m0,  v.x + adn0);
                m1_ = fmaxf(m1_, v.y + adn1);
                m2_ = fmaxf(m2_, v.z + adn2);
                m3_ = fmaxf(m3_, v.w + adn3);
            }
#pragma unroll
            for (int off = 16; off; off >>= 1) {
                m0  = fmaxf(m0,  __shfl_xor_sync(0xffffffffu, m0, off));
                m1_ = fmaxf(m1_, __shfl_xor_sync(0xffffffffu, m1_, off));
                m2_ = fmaxf(m2_, __shfl_xor_sync(0xffffffffu, m2_, off));
                m3_ = fmaxf(m3_, __shfl_xor_sync(0xffffffffu, m3_, off));
            }
            float mx  = lrelu((myh == 0) ? m0 : (myh == 1) ? m1_ : (myh == 2) ? m2_ : m3_);
            float adn = (myh == 0) ? adn0 : (myh == 1) ? adn1 : (myh == 2) ? adn2 : adn3;

            float4 acc = make_float4(0.f, 0.f, 0.f, 0.f);
            float den = 0.f;
            int e = 0;
            for (; e + 4 <= cnt; e += 4) {
                int s0 = __ldg(pl + e + 0), s1 = __ldg(pl + e + 1);
                int s2 = __ldg(pl + e + 2), s3 = __ldg(pl + e + 3);
                uint2 r0 = __ldg(hb + (size_t)s0 * 32 + lane);
                uint2 r1 = __ldg(hb + (size_t)s1 * 32 + lane);
                uint2 r2 = __ldg(hb + (size_t)s2 * 32 + lane);
                uint2 r3 = __ldg(hb + (size_t)s3 * 32 + lane);
                float w0 = __expf(lrelu(__ldg(&g_as[s0 * 4 + myh]) + adn) - mx);
                float w1 = __expf(lrelu(__ldg(&g_as[s1 * 4 + myh]) + adn) - mx);
                float w2 = __expf(lrelu(__ldg(&g_as[s2 * 4 + myh]) + adn) - mx);
                float w3 = __expf(lrelu(__ldg(&g_as[s3 * 4 + myh]) + adn) - mx);
                den += (w0 + w1) + (w2 + w3);
                float2 a0 = bf2f(r0.x), b0 = bf2f(r0.y);
                float2 a1 = bf2f(r1.x), b1 = bf2f(r1.y);
                float2 a2 = bf2f(r2.x), b2 = bf2f(r2.y);
                float2 a3 = bf2f(r3.x), b3 = bf2f(r3.y);
                acc.x += w0 * a0.x + w1 * a1.x + w2 * a2.x + w3 * a3.x;
                acc.y += w0 * a0.y + w1 * a1.y + w2 * a2.y + w3 * a3.y;
                acc.z += w0 * b0.x + w1 * b1.x + w2 * b2.x + w3 * b3.x;
                acc.w += w0 * b0.y + w1 * b1.y + w2 * b2.y + w3 * b3.y;
            }
            for (; e <= cnt; e++) {
                int sn = (e < cnt) ? __ldg(pl + e) : nId;
                float w = __expf(lrelu(__ldg(&g_as[sn * 4 + myh]) + adn) - mx);
                den += w;
                uint2 r = __ldg(hb + (size_t)sn * 32 + lane);
                float2 a = bf2f(r.x), b = bf2f(r.y);
                acc.x += w * a.x; acc.y += w * a.y; acc.z += w * b.x; acc.w += w * b.y;
            }
            float inv = 1.f / den;
            acc.x *= inv; acc.y *= inv; acc.z *= inv; acc.w *= inv;
#pragma unroll
            for (int off = 8; off <= 16; off <<= 1) {
                acc.x += __shfl_xor_sync(0xffffffffu, acc.x, off);
                acc.y += __shfl_xor_sync(0xffffffffu, acc.y, off);
                acc.z += __shfl_xor_sync(0xffffffffu, acc.z, off);
                acc.w += __shfl_xor_sync(0xffffffffu, acc.w, off);
            }
            if (lane < 8) {
                float4 bgv = __ldg(reinterpret_cast<const float4*>(bg) + lane);
                int b = __ldg(batch + nId);
                float* p = &g_pool[b * 32 + lane * 4];
                atomicAdd(p + 0, fmaxf(acc.x * 0.25f + bgv.x, 0.f));
                atomicAdd(p + 1, fmaxf(acc.y * 0.25f + bgv.y, 0.f));
                atomicAdd(p + 2, fmaxf(acc.z * 0.25f + bgv.z, 0.f));
                atomicAdd(p + 3, fmaxf(acc.w * 0.25f + bgv.w, 0.f));
                if (lane == 0) atomicAdd(&g_cnt[b], 1.f);
            }
        }
    }
    gridbar();

    // S12: classifier head (block 0 only)
    if (blockIdx.x == 0) {
        float* pooled = smw;
        float* hid = smw + GMAX * 32;
        for (int t = tid; t < G * 32; t += NTHR) pooled[t] = g_pool[t] / fmaxf(g_cnt[t >> 5], 1.f);
        __syncthreads();
        for (int t = tid; t < G * 16; t += NTHR) {
            int g = t >> 4, j = t & 15;
            float s = __ldg(bc1 + j);
            for (int k = 0; k < 32; k++) s += pooled[g * 32 + k] * __ldg(Wc1 + k * 16 + j);
            hid[t] = fmaxf(s, 0.f);
        }
        __syncthreads();
        for (int t = tid; t < G * 5; t += NTHR) {
            int g = t / 5, c = t % 5;
            float s = __ldg(bc2 + c);
            for (int k = 0; k < 16; k++) s += hid[g * 16 + k] * __ldg(Wc2 + k * 5 + c);
            out[t] = s;
        }
    }
}

// ---------------- host ----------------
extern "C" void kernel_launch(void* const* d_in, const int* in_sizes, int n_in,
                              void* d_out, int out_size) {
    const float* x = (const float*)d_in[0];
    const int* ei = (const int*)d_in[1];
    const int* batch = (const int*)d_in[2];
    int n = in_sizes[0] / 64;
    int E = in_sizes[1] / 2;
    int G = out_size / 5;

    const float *W1, *b1, *W2, *b2, *W3, *b3;
    const float *g1, *be1, *m1, *v1, *g2, *be2, *m2, *v2, *g3, *be3, *m3, *v3;
    const float *Wg, *ags, *agd, *bg, *Wc1, *bc1, *Wc2, *bc2;

    if (in_sizes[5] == 128 * 64) {
        W1 = (const float*)d_in[3];  b1 = (const float*)d_in[4];
        W2 = (const float*)d_in[5];  b2 = (const float*)d_in[6];
        W3 = (const float*)d_in[7];  b3 = (const float*)d_in[8];
        g1 = (const float*)d_in[9];  be1 = (const float*)d_in[10];
        m1 = (const float*)d_in[11]; v1 = (const float*)d_in[12];
        g2 = (const float*)d_in[13]; be2 = (const float*)d_in[14];
        m2 = (const float*)d_in[15]; v2 = (const float*)d_in[16];
        g3 = (const float*)d_in[17]; be3 = (const float*)d_in[18];
        m3 = (const float*)d_in[19]; v3 = (const float*)d_in[20];
        Wg = (const float*)d_in[21]; ags = (const float*)d_in[22];
        agd = (const float*)d_in[23]; bg = (const float*)d_in[24];
        Wc1 = (const float*)d_in[25]; bc1 = (const float*)d_in[26];
        Wc2 = (const float*)d_in[27]; bc2 = (const float*)d_in[28];
    } else {
        W1 = (const float*)d_in[3];  b1 = (const float*)d_in[4];
        g1 = (const float*)d_in[5];  be1 = (const float*)d_in[6];
        m1 = (const float*)d_in[7];  v1 = (const float*)d_in[8];
        W2 = (const float*)d_in[9];  b2 = (const float*)d_in[10];
        g2 = (const float*)d_in[11]; be2 = (const float*)d_in[12];
        m2 = (const float*)d_in[13]; v2 = (const float*)d_in[14];
        W3 = (const float*)d_in[15]; b3 = (const float*)d_in[16];
        g3 = (const float*)d_in[17]; be3 = (const float*)d_in[18];
        m3 = (const float*)d_in[19]; v3 = (const float*)d_in[20];
        Wg = (const float*)d_in[21]; ags = (const float*)d_in[22];
        agd = (const float*)d_in[23]; bg = (const float*)d_in[24];
        Wc1 = (const float*)d_in[25]; bc1 = (const float*)d_in[26];
        Wc2 = (const float*)d_in[27]; bc2 = (const float*)d_in[28];
    }

    const int* src = ei;
    const int* dst = ei + E;

    k_mega<<<NBLK, NTHR>>>(x, src, dst, batch, n, E, G,
                           W1, b1, g1, be1, m1, v1,
                           W2, b2, g2, be2, m2, v2,
                           W3, b3, g3, be3, m3, v3,
                           Wg, ags, agd, bg,
                           Wc1, bc1, Wc2, bc2,
                           (float*)d_out);
}

// round 8
// speedup vs baseline: 1.2574x; 1.2139x over previous
#include <cuda_runtime.h>
#include <cuda_bf16.h>
#include <math_constants.h>

#define NMAX 100000
#define GMAX 64
#define SLOTS 64
#define EPS 1e-5f
#define NEG_SLOPE 0.2f
#define NBLK 592          // 148 SMs x 4 blocks, all co-resident
#define NTHR 256

// ---------------- scratch (device globals) ----------------
__device__ __align__(16) float g_bufA[NMAX * 128];
__device__ __align__(16) float g_bufB[NMAX * 128];
__device__ __align__(16) unsigned g_hh[NMAX * 64];   // bf16x2 (up to 128 cols/node)
__device__ __align__(16) unsigned g_xbf[NMAX * 32];  // bf16x2 (up to 64 cols/node)
__device__ float g_dinv[NMAX];
__device__ int   g_deg[NMAX];
__device__ int   g_cursor[NMAX];
__device__ int   g_perm[NMAX * SLOTS];
__device__ __align__(16) float g_as[NMAX * 4];
__device__ float g_ad[NMAX * 4];
__device__ float g_pool[GMAX * 32];
__device__ float g_cnt[GMAX];
__device__ unsigned g_gen  = 0;
__device__ unsigned g_bcnt = 0;

// ---------------- grid-wide barrier ----------------
__device__ __forceinline__ void gridbar() {
    __syncthreads();
    if (threadIdx.x == 0) {
        unsigned my = atomicAdd(&g_gen, 0u);
        __threadfence();
        if (atomicAdd(&g_bcnt, 1u) == NBLK - 1u) {
            atomicExch(&g_bcnt, 0u);
            __threadfence();
            atomicAdd(&g_gen, 1u);
        } else {
            while (atomicAdd(&g_gen, 0u) == my) __nanosleep(64);
        }
        __threadfence();
    }
    __syncthreads();
}

__device__ __forceinline__ float lrelu(float x) { return x > 0.f ? x : NEG_SLOPE * x; }
__device__ __forceinline__ float2 bf2f(unsigned u) {
    return __bfloat1622float2(*reinterpret_cast<const __nv_bfloat162*>(&u));
}
__device__ __forceinline__ unsigned f2bf(float a, float b) {
    __nv_bfloat162 p = __floats2bfloat162_rn(a, b);
    return *reinterpret_cast<unsigned*>(&p);
}
__device__ __forceinline__ unsigned f2tf(float f) {
    unsigned u;
    asm("cvt.rna.tf32.f32 %0, %1;" : "=r"(u) : "f"(f));
    return u;
}

__shared__ __align__(16) float smw[10240];   // 40KB stage scratch

// ---------------- tensor-core MMA m16n8k8 tf32 -> fp32 ----------------
__device__ __forceinline__ void mma1688(float c[4], unsigned a0, unsigned a1,
                                        unsigned a2, unsigned a3, unsigned b0, unsigned b1) {
    asm volatile(
        "mma.sync.aligned.m16n8k8.row.col.f32.tf32.tf32.f32 "
        "{%0,%1,%2,%3}, {%4,%5,%6,%7}, {%8,%9}, {%0,%1,%2,%3};"
        : "+f"(c[0]), "+f"(c[1]), "+f"(c[2]), "+f"(c[3])
        : "r"(a0), "r"(a1), "r"(a2), "r"(a3), "r"(b0), "r"(b1));
}

// ---------------- GEMM via tf32 MMA: A fp32 -> C fp32 or bf16, opt bias+BN+relu ----------------
template <int KIN, int KOUT, bool EPI, bool BOUT>
__device__ void stage_mma(const float* __restrict__ A, float* __restrict__ Cf,
                          unsigned* __restrict__ Cb,
                          const float* __restrict__ W, int n, int lane, int gw, int GW,
                          const float* __restrict__ bias, const float* __restrict__ gam,
                          const float* __restrict__ bet, const float* __restrict__ mu,
                          const float* __restrict__ var) {
    constexpr int KS = KIN / 8;         // k-steps (k8)
    constexpr int NT = KOUT / 8;        // n-tiles
    constexpr int JT = (NT >= 4) ? 4 : NT;
    constexpr int CHUNKS = NT / JT;
    constexpr int KOUT2 = KOUT / 2;

    // stage W fragments (tf32) in smem: bsm[(j*KS+s)*32 + lane] = {W[8s+c][nn], W[8s+4+c][nn]}
    uint2* bsm = reinterpret_cast<uint2*>(smw);   // up to 32KB
    for (int i = threadIdx.x; i < NT * KS * 32; i += NTHR) {
        int j = i / (KS * 32);
        int rem = i - j * (KS * 32);
        int s = rem >> 5;
        int l = rem & 31;
        int c_ = l & 3, nn = 8 * j + (l >> 2);
        int k0 = 8 * s + c_;
        unsigned v0 = f2tf(__ldg(W + k0 * KOUT + nn));
        unsigned v1 = f2tf(__ldg(W + (k0 + 4) * KOUT + nn));
        bsm[i] = make_uint2(v0, v1);
    }
    float* epiA = smw + 8192;
    float* epiB = smw + 8192 + KOUT;
    if constexpr (EPI) {
        for (int cix = threadIdx.x; cix < KOUT; cix += NTHR) {
            float Av = __ldg(gam + cix) * rsqrtf(__ldg(var + cix) + EPS);
            epiA[cix] = Av;
            epiB[cix] = __ldg(bet + cix) + (__ldg(bias + cix) - __ldg(mu + cix)) * Av;
        }
    }
    __syncthreads();

    int nrt = (n + 15) >> 4;
    int c = lane & 3, q = lane >> 2;
    for (int T = gw; T < nrt * CHUNKS; T += GW) {
        int rt = T / CHUNKS;
        int ch = T - rt * CHUNKS;
        int r0 = rt * 16 + q;
        int r1 = r0 + 8;
        int rA = r0 < n ? r0 : n - 1;
        int rB = r1 < n ? r1 : n - 1;
        const float* arow0 = A + (size_t)rA * KIN;
        const float* arow1 = A + (size_t)rB * KIN;
        float acc[JT][4];
#pragma unroll
        for (int jj = 0; jj < JT; jj++) {
            acc[jj][0] = 0.f; acc[jj][1] = 0.f; acc[jj][2] = 0.f; acc[jj][3] = 0.f;
        }
#pragma unroll
        for (int s = 0; s < KS; s++) {
            unsigned a0 = f2tf(__ldg(arow0 + 8 * s + c));
            unsigned a1 = f2tf(__ldg(arow1 + 8 * s + c));
            unsigned a2 = f2tf(__ldg(arow0 + 8 * s + 4 + c));
            unsigned a3 = f2tf(__ldg(arow1 + 8 * s + 4 + c));
#pragma unroll
            for (int jj = 0; jj < JT; jj++) {
                uint2 bb = bsm[((ch * JT + jj) * KS + s) * 32 + lane];
                mma1688(acc[jj], a0, a1, a2, a3, bb.x, bb.y);
            }
        }
#pragma unroll
        for (int jj = 0; jj < JT; jj++) {
            int col0 = 8 * (ch * JT + jj) + 2 * c;
            float x0 = acc[jj][0], x1 = acc[jj][1], x2 = acc[jj][2], x3 = acc[jj][3];
            if constexpr (EPI) {
                float A0 = epiA[col0], B0 = epiB[col0];
                float A1 = epiA[col0 + 1], B1 = epiB[col0 + 1];
                x0 = fmaxf(x0 * A0 + B0, 0.f); x1 = fmaxf(x1 * A1 + B1, 0.f);
                x2 = fmaxf(x2 * A0 + B0, 0.f); x3 = fmaxf(x3 * A1 + B1, 0.f);
            }
            if constexpr (BOUT) {
                int ci = col0 >> 1;
                if (r0 < n) Cb[(size_t)r0 * KOUT2 + ci] = f2bf(x0, x1);
                if (r1 < n) Cb[(size_t)r1 * KOUT2 + ci] = f2bf(x2, x3);
            } else {
                if (r0 < n)
                    *reinterpret_cast<float2*>(Cf + (size_t)r0 * KOUT + col0) = make_float2(x0, x1);
                if (r1 < n)
                    *reinterpret_cast<float2*>(Cf + (size_t)r1 * KOUT + col0) = make_float2(x2, x3);
            }
        }
    }
}

// ---------------- GCN aggregation from bf16 features, fp32 accumulate/output ----------------
template <int D, bool EPIL>
__device__ void stage_agg_bf(const unsigned* __restrict__ featb, float* __restrict__ out, int n,
                             int lane, int gw, int GW,
                             const float* __restrict__ bias, const float* __restrict__ gam,
                             const float* __restrict__ bet, const float* __restrict__ mu,
                             const float* __restrict__ var) {
    constexpr int PR = D / 2;
    int li = lane & (PR - 1);
    float A0 = 1.f, A1 = 1.f, B0 = 0.f, B1 = 0.f;
    if constexpr (EPIL) {
        int d0 = 2 * li, d1 = 2 * li + 1;
        A0 = __ldg(gam + d0) * rsqrtf(__ldg(var + d0) + EPS);
        B0 = __ldg(bet + d0) + (__ldg(bias + d0) - __ldg(mu + d0)) * A0;
        A1 = __ldg(gam + d1) * rsqrtf(__ldg(var + d1) + EPS);
        B1 = __ldg(bet + d1) + (__ldg(bias + d1) - __ldg(mu + d1)) * A1;
    }
    for (int w = gw; w < n; w += GW) {
        float di = g_dinv[w];
        int cnt = g_deg[w];
        const int* __restrict__ pl = g_perm + (size_t)w * SLOTS;
        float ax, ay;
        {
            float nm = di * di;
            float2 v = bf2f(__ldg(featb + (size_t)w * PR + li));
            ax = nm * v.x; ay = nm * v.y;
        }
        int e = 0;
        for (; e + 8 <= cnt; e += 8) {
            int s[8]; float nm[8]; unsigned r[8];
#pragma unroll
            for (int u = 0; u < 8; u++) s[u] = __ldg(pl + e + u);
#pragma unroll
            for (int u = 0; u < 8; u++) r[u] = __ldg(featb + (size_t)s[u] * PR + li);
#pragma unroll
            for (int u = 0; u < 8; u++) nm[u] = di * __ldg(g_dinv + s[u]);
#pragma unroll
            for (int u = 0; u < 8; u++) {
                float2 v = bf2f(r[u]);
                ax += nm[u] * v.x; ay += nm[u] * v.y;
            }
        }
        for (; e + 4 <= cnt; e += 4) {
            int s[4]; float nm[4]; unsigned r[4];
#pragma unroll
            for (int u = 0; u < 4; u++) s[u] = __ldg(pl + e + u);
#pragma unroll
            for (int u = 0; u < 4; u++) r[u] = __ldg(featb + (size_t)s[u] * PR + li);
#pragma unroll
            for (int u = 0; u < 4; u++) nm[u] = di * __ldg(g_dinv + s[u]);
#pragma unroll
            for (int u = 0; u < 4; u++) {
                float2 v = bf2f(r[u]);
                ax += nm[u] * v.x; ay += nm[u] * v.y;
            }
        }
        for (; e < cnt; e++) {
            int sn = __ldg(pl + e);
            float nm = di * __ldg(g_dinv + sn);
            float2 v = bf2f(__ldg(featb + (size_t)sn * PR + li));
            ax += nm * v.x; ay += nm * v.y;
        }
        if constexpr (EPIL) {
            ax = fmaxf(ax * A0 + B0, 0.f);
            ay = fmaxf(ay * A1 + B1, 0.f);
        }
        if (lane < PR)
            *reinterpret_cast<float2*>(out + (size_t)w * D + li * 2) = make_float2(ax, ay);
    }
}

// ---------------- the megakernel ----------------
__global__ void __launch_bounds__(NTHR, 4)
k_mega(const float* __restrict__ x, const int* __restrict__ src, const int* __restrict__ dst,
       const int* __restrict__ batch, int n, int E, int G,
       const float* W1, const float* b1, const float* g1, const float* be1, const float* m1, const float* v1,
       const float* W2, const float* b2, const float* g2, const float* be2, const float* m2, const float* v2,
       const float* W3, const float* b3, const float* g3, const float* be3, const float* m3, const float* v3,
       const float* Wg, const float* ags, const float* agd, const float* bg,
       const float* Wc1, const float* bc1, const float* Wc2, const float* bc2,
       float* __restrict__ out) {
    int tid = threadIdx.x;
    int lane = tid & 31;
    int gt = blockIdx.x * NTHR + tid;
    int gw = gt >> 5;
    const int GT = NBLK * NTHR;
    const int GW = GT / 32;

    // S0: zero cursors/pool/cnt + convert x -> bf16
    for (int i = gt; i < n; i += GT) g_cursor[i] = 0;
    if (gt < GMAX * 32) g_pool[gt] = 0.f;
    if (gt < GMAX) g_cnt[gt] = 0.f;
    for (int i = gt; i < n * 32; i += GT)
        g_xbf[i] = f2bf(__ldg(x + 2 * i), __ldg(x + 2 * i + 1));
    gridbar();

    // S1: bucket scatter by dst
    for (int e = gt; e < E; e += GT) {
        int d = dst[e];
        int slot = atomicAdd(&g_cursor[d], 1);
        if (slot < SLOTS) g_perm[(size_t)d * SLOTS + slot] = src[e];
    }
    gridbar();

    // S2: finalize degree / dinv
    for (int i = gt; i < n; i += GT) {
        int c = g_cursor[i];
        if (c > SLOTS) c = SLOTS;
        g_deg[i] = c;
        g_dinv[i] = rsqrtf((float)(c + 1));
    }
    gridbar();

    // S3: aggregate bf16 input (linearity), fp32 out
    stage_agg_bf<64, false>(g_xbf, g_bufA, n, lane, gw, GW, nullptr, nullptr, nullptr, nullptr, nullptr);
    gridbar();

    // S4: tf32 GEMM 64->128 + bias/BN/relu, fp32 out
    stage_mma<64, 128, true, false>(g_bufA, g_bufB, nullptr, W1, n, lane, gw, GW, b1, g1, be1, m1, v1);
    gridbar();

    // S5: tf32 GEMM 128->64, bf16 out
    stage_mma<128, 64, false, true>(g_bufB, nullptr, g_hh, W2, n, lane, gw, GW, nullptr, nullptr, nullptr, nullptr, nullptr);
    gridbar();

    // S6: aggregate bf16 + bias/BN/relu, fp32 out
    stage_agg_bf<64, true>(g_hh, g_bufA, n, lane, gw, GW, b2, g2, be2, m2, v2);
    gridbar();

    // S7: tf32 GEMM 64->32, bf16 out
    stage_mma<64, 32, false, true>(g_bufA, nullptr, g_xbf, W3, n, lane, gw, GW, nullptr, nullptr, nullptr, nullptr, nullptr);
    gridbar();

    // S8: aggregate bf16 + bias/BN/relu, fp32 out (32-dim)
    stage_agg_bf<32, true>(g_xbf, g_bufB, n, lane, gw, GW, b3, g3, be3, m3, v3);
    gridbar();

    // S9: tf32 GEMM 32->128 (GAT projection), fp32 out
    stage_mma<32, 128, false, false>(g_bufB, g_bufA, nullptr, Wg, n, lane, gw, GW, nullptr, nullptr, nullptr, nullptr, nullptr);
    gridbar();

    // S10: attention coefficients + bf16 copy of hh
    for (int i = tid; i < 128; i += NTHR) { smw[i] = ags[i]; smw[128 + i] = agd[i]; }
    __syncthreads();
    for (int t = gt; t < n * 4; t += GT) {
        int node = t >> 2, h = t & 3;
        const float* row = g_bufA + (size_t)node * 128 + h * 32;
        float s = 0.f, d = 0.f;
        unsigned* hrow = g_hh + (size_t)node * 64 + h * 16;
#pragma unroll
        for (int k = 0; k < 16; k++) {
            float x0 = __ldg(row + 2 * k);
            float x1 = __ldg(row + 2 * k + 1);
            s += x0 * smw[h * 32 + 2 * k] + x1 * smw[h * 32 + 2 * k + 1];
            d += x0 * smw[128 + h * 32 + 2 * k] + x1 * smw[128 + h * 32 + 2 * k + 1];
            hrow[k] = f2bf(x0, x1);
        }
        g_as[t] = s;
        g_ad[t] = d;
    }
    gridbar();

    // S11: GAT aggregation (bf16 gather) + bias/relu + fused pool
    {
        const uint2* hb = reinterpret_cast<const uint2*>(g_hh);
        int myh = lane >> 3;
        for (int nId = gw; nId < n; nId += GW) {
            const int* __restrict__ pl = g_perm + (size_t)nId * SLOTS;
            int cnt = g_deg[nId];
            float adn0 = __ldg(&g_ad[nId * 4 + 0]);
            float adn1 = __ldg(&g_ad[nId * 4 + 1]);
            float adn2 = __ldg(&g_ad[nId * 4 + 2]);
            float adn3 = __ldg(&g_ad[nId * 4 + 3]);

            float m0 = -CUDART_INF_F, m1_ = -CUDART_INF_F, m2_ = -CUDART_INF_F, m3_ = -CUDART_INF_F;
            for (int e = lane; e <= cnt; e += 32) {
                int sn = (e < cnt) ? __ldg(pl + e) : nId;
                float4 v = __ldg(reinterpret_cast<const float4*>(g_as) + sn);
                m0  = fmaxf(m0,  v.x + adn0);
                m1_ = fmaxf(m1_, v.y + adn1);
                m2_ = fmaxf(m2_, v.z + adn2);
                m3_ = fmaxf(m3_, v.w + adn3);
            }
#pragma unroll
            for (int off = 16; off; off >>= 1) {
                m0  = fmaxf(m0,  __shfl_xor_sync(0xffffffffu, m0, off));
                m1_ = fmaxf(m1_, __shfl_xor_sync(0xffffffffu, m1_, off));
                m2_ = fmaxf(m2_, __shfl_xor_sync(0xffffffffu, m2_, off));
                m3_ = fmaxf(m3_, __shfl_xor_sync(0xffffffffu, m3_, off));
            }
            float mx  = lrelu((myh == 0) ? m0 : (myh == 1) ? m1_ : (myh == 2) ? m2_ : m3_);
            float adn = (myh == 0) ? adn0 : (myh == 1) ? adn1 : (myh == 2) ? adn2 : adn3;

            float4 acc = make_float4(0.f, 0.f, 0.f, 0.f);
            float den = 0.f;
            int e = 0;
            for (; e + 4 <= cnt; e += 4) {
                int s0 = __ldg(pl + e + 0), s1 = __ldg(pl + e + 1);
                int s2 = __ldg(pl + e + 2), s3 = __ldg(pl + e + 3);
                uint2 r0 = __ldg(hb + (size_t)s0 * 32 + lane);
                uint2 r1 = __ldg(hb + (size_t)s1 * 32 + lane);
                uint2 r2 = __ldg(hb + (size_t)s2 * 32 + lane);
                uint2 r3 = __ldg(hb + (size_t)s3 * 32 + lane);
                float w0 = __expf(lrelu(__ldg(&g_as[s0 * 4 + myh]) + adn) - mx);
                float w1 = __expf(lrelu(__ldg(&g_as[s1 * 4 + myh]) + adn) - mx);
                float w2 = __expf(lrelu(__ldg(&g_as[s2 * 4 + myh]) + adn) - mx);
                float w3 = __expf(lrelu(__ldg(&g_as[s3 * 4 + myh]) + adn) - mx);
                den += (w0 + w1) + (w2 + w3);
                float2 a0 = bf2f(r0.x), b0 = bf2f(r0.y);
                float2 a1 = bf2f(r1.x), b1 = bf2f(r1.y);
                float2 a2 = bf2f(r2.x), b2 = bf2f(r2.y);
                float2 a3 = bf2f(r3.x), b3 = bf2f(r3.y);
                acc.x += w0 * a0.x + w1 * a1.x + w2 * a2.x + w3 * a3.x;
                acc.y += w0 * a0.y + w1 * a1.y + w2 * a2.y + w3 * a3.y;
                acc.z += w0 * b0.x + w1 * b1.x + w2 * b2.x + w3 * b3.x;
                acc.w += w0 * b0.y + w1 * b1.y + w2 * b2.y + w3 * b3.y;
            }
            for (; e <= cnt; e++) {
                int sn = (e < cnt) ? __ldg(pl + e) : nId;
                float w = __expf(lrelu(__ldg(&g_as[sn * 4 + myh]) + adn) - mx);
                den += w;
                uint2 r = __ldg(hb + (size_t)sn * 32 + lane);
                float2 a = bf2f(r.x), b = bf2f(r.y);
                acc.x += w * a.x; acc.y += w * a.y; acc.z += w * b.x; acc.w += w * b.y;
            }
            float inv = 1.f / den;
            acc.x *= inv; acc.y *= inv; acc.z *= inv; acc.w *= inv;
#pragma unroll
            for (int off = 8; off <= 16; off <<= 1) {
                acc.x += __shfl_xor_sync(0xffffffffu, acc.x, off);
                acc.y += __shfl_xor_sync(0xffffffffu, acc.y, off);
                acc.z += __shfl_xor_sync(0xffffffffu, acc.z, off);
                acc.w += __shfl_xor_sync(0xffffffffu, acc.w, off);
            }
            if (lane < 8) {
                float4 bgv = __ldg(reinterpret_cast<const float4*>(bg) + lane);
                int b = __ldg(batch + nId);
                float* p = &g_pool[b * 32 + lane * 4];
                atomicAdd(p + 0, fmaxf(acc.x * 0.25f + bgv.x, 0.f));
                atomicAdd(p + 1, fmaxf(acc.y * 0.25f + bgv.y, 0.f));
                atomicAdd(p + 2, fmaxf(acc.z * 0.25f + bgv.z, 0.f));
                atomicAdd(p + 3, fmaxf(acc.w * 0.25f + bgv.w, 0.f));
                if (lane == 0) atomicAdd(&g_cnt[b], 1.f);
            }
        }
    }
    gridbar();

    // S12: classifier head (block 0 only)
    if (blockIdx.x == 0) {
        float* pooled = smw;
        float* hid = smw + GMAX * 32;
        for (int t = tid; t < G * 32; t += NTHR) pooled[t] = g_pool[t] / fmaxf(g_cnt[t >> 5], 1.f);
        __syncthreads();
        for (int t = tid; t < G * 16; t += NTHR) {
            int g = t >> 4, j = t & 15;
            float s = __ldg(bc1 + j);
            for (int k = 0; k < 32; k++) s += pooled[g * 32 + k] * __ldg(Wc1 + k * 16 + j);
            hid[t] = fmaxf(s, 0.f);
        }
        __syncthreads();
        for (int t = tid; t < G * 5; t += NTHR) {
            int g = t / 5, c = t % 5;
            float s = __ldg(bc2 + c);
            for (int k = 0; k < 16; k++) s += hid[g * 16 + k] * __ldg(Wc2 + k * 5 + c);
            out[t] = s;
        }
    }
}

// ---------------- host ----------------
extern "C" void kernel_launch(void* const* d_in, const int* in_sizes, int n_in,
                              void* d_out, int out_size) {
    const float* x = (const float*)d_in[0];
    const int* ei = (const int*)d_in[1];
    const int* batch = (const int*)d_in[2];
    int n = in_sizes[0] / 64;
    int E = in_sizes[1] / 2;
    int G = out_size / 5;

    const float *W1, *b1, *W2, *b2, *W3, *b3;
    const float *g1, *be1, *m1, *v1, *g2, *be2, *m2, *v2, *g3, *be3, *m3, *v3;
    const float *Wg, *ags, *agd, *bg, *Wc1, *bc1, *Wc2, *bc2;

    if (in_sizes[5] == 128 * 64) {
        W1 = (const float*)d_in[3];  b1 = (const float*)d_in[4];
        W2 = (const float*)d_in[5];  b2 = (const float*)d_in[6];
        W3 = (const float*)d_in[7];  b3 = (const float*)d_in[8];
        g1 = (const float*)d_in[9];  be1 = (const float*)d_in[10];
        m1 = (const float*)d_in[11]; v1 = (const float*)d_in[12];
        g2 = (const float*)d_in[13]; be2 = (const float*)d_in[14];
        m2 = (const float*)d_in[15]; v2 = (const float*)d_in[16];
        g3 = (const float*)d_in[17]; be3 = (const float*)d_in[18];
        m3 = (const float*)d_in[19]; v3 = (const float*)d_in[20];
        Wg = (const float*)d_in[21]; ags = (const float*)d_in[22];
        agd = (const float*)d_in[23]; bg = (const float*)d_in[24];
        Wc1 = (const float*)d_in[25]; bc1 = (const float*)d_in[26];
        Wc2 = (const float*)d_in[27]; bc2 = (const float*)d_in[28];
    } else {
        W1 = (const float*)d_in[3];  b1 = (const float*)d_in[4];
        g1 = (const float*)d_in[5];  be1 = (const float*)d_in[6];
        m1 = (const float*)d_in[7];  v1 = (const float*)d_in[8];
        W2 = (const float*)d_in[9];  b2 = (const float*)d_in[10];
        g2 = (const float*)d_in[11]; be2 = (const float*)d_in[12];
        m2 = (const float*)d_in[13]; v2 = (const float*)d_in[14];
        W3 = (const float*)d_in[15]; b3 = (const float*)d_in[16];
        g3 = (const float*)d_in[17]; be3 = (const float*)d_in[18];
        m3 = (const float*)d_in[19]; v3 = (const float*)d_in[20];
        Wg = (const float*)d_in[21]; ags = (const float*)d_in[22];
        agd = (const float*)d_in[23]; bg = (const float*)d_in[24];
        Wc1 = (const float*)d_in[25]; bc1 = (const float*)d_in[26];
        Wc2 = (const float*)d_in[27]; bc2 = (const float*)d_in[28];
    }

    const int* src = ei;
    const int* dst = ei + E;

    k_mega<<<NBLK, NTHR>>>(x, src, dst, batch, n, E, G,
                           W1, b1, g1, be1, m1, v1,
                           W2, b2, g2, be2, m2, v2,
                           W3, b3, g3, be3, m3, v3,
                           Wg, ags, agd, bg,
                           Wc1, bc1, Wc2, bc2,
                           (float*)d_out);
}

// round 9
// speedup vs baseline: 1.5062x; 1.1979x over previous
#include <cuda_runtime.h>
#include <cuda_bf16.h>
#include <math_constants.h>

#define NMAX 100000
#define GMAX 64
#define SLOTS 64
#define EPS 1e-5f
#define NEG_SLOPE 0.2f
#define NBLK 592          // 148 SMs x 4 blocks, all co-resident
#define NTHR 256

// ---------------- scratch (device globals) ----------------
__device__ __align__(16) float g_bufA[NMAX * 128];
__device__ __align__(16) float g_bufB[NMAX * 128];
__device__ __align__(16) unsigned g_hh[NMAX * 64];   // bf16x2 (up to 128 cols/node)
__device__ __align__(16) unsigned g_xbf[NMAX * 32];  // bf16x2 (up to 64 cols/node)
__device__ float g_dinv[NMAX];
__device__ int   g_deg[NMAX];
__device__ int   g_cursor[NMAX];
__device__ int   g_perm[NMAX * SLOTS];
__device__ __align__(16) float g_as[NMAX * 4];
__device__ float g_ad[NMAX * 4];
__device__ float g_pool[GMAX * 32];
__device__ float g_cnt[GMAX];
__device__ unsigned g_gen  = 0;
__device__ unsigned g_bcnt = 0;

// ---------------- grid-wide barrier ----------------
__device__ __forceinline__ void gridbar() {
    __syncthreads();
    if (threadIdx.x == 0) {
        unsigned my = atomicAdd(&g_gen, 0u);
        __threadfence();
        if (atomicAdd(&g_bcnt, 1u) == NBLK - 1u) {
            atomicExch(&g_bcnt, 0u);
            __threadfence();
            atomicAdd(&g_gen, 1u);
        } else {
            while (atomicAdd(&g_gen, 0u) == my) __nanosleep(64);
        }
        __threadfence();
    }
    __syncthreads();
}

__device__ __forceinline__ float lrelu(float x) { return x > 0.f ? x : NEG_SLOPE * x; }
__device__ __forceinline__ float2 bf2f(unsigned u) {
    return __bfloat1622float2(*reinterpret_cast<const __nv_bfloat162*>(&u));
}
__device__ __forceinline__ unsigned f2bf(float a, float b) {
    __nv_bfloat162 p = __floats2bfloat162_rn(a, b);
    return *reinterpret_cast<unsigned*>(&p);
}
__device__ __forceinline__ unsigned f2tf(float f) {
    unsigned u;
    asm("cvt.rna.tf32.f32 %0, %1;" : "=r"(u) : "f"(f));
    return u;
}

__shared__ __align__(16) float smw[10240];   // 40KB stage scratch

// ---------------- tensor-core MMA m16n8k8 tf32 -> fp32 ----------------
__device__ __forceinline__ void mma1688(float c[4], unsigned a0, unsigned a1,
                                        unsigned a2, unsigned a3, unsigned b0, unsigned b1) {
    asm volatile(
        "mma.sync.aligned.m16n8k8.row.col.f32.tf32.tf32.f32 "
        "{%0,%1,%2,%3}, {%4,%5,%6,%7}, {%8,%9}, {%0,%1,%2,%3};"
        : "+f"(c[0]), "+f"(c[1]), "+f"(c[2]), "+f"(c[3])
        : "r"(a0), "r"(a1), "r"(a2), "r"(a3), "r"(b0), "r"(b1));
}

// ---------------- GEMM via tf32 MMA: A fp32 -> C fp32 or bf16, opt bias+BN+relu ----------------
template <int KIN, int KOUT, bool EPI, bool BOUT>
__device__ void stage_mma(const float* __restrict__ A, float* __restrict__ Cf,
                          unsigned* __restrict__ Cb,
                          const float* __restrict__ W, int n, int lane, int gw, int GW,
                          const float* __restrict__ bias, const float* __restrict__ gam,
                          const float* __restrict__ bet, const float* __restrict__ mu,
                          const float* __restrict__ var) {
    constexpr int KS = KIN / 8;         // k-steps (k8)
    constexpr int NT = KOUT / 8;        // n-tiles
    constexpr int JT = (NT >= 8) ? 8 : NT;   // n-tiles per task (n64) -> less A-load duplication
    constexpr int CHUNKS = NT / JT;
    constexpr int KOUT2 = KOUT / 2;

    // stage W fragments (tf32) in smem
    uint2* bsm = reinterpret_cast<uint2*>(smw);   // up to 32KB
    for (int i = threadIdx.x; i < NT * KS * 32; i += NTHR) {
        int j = i / (KS * 32);
        int rem = i - j * (KS * 32);
        int s = rem >> 5;
        int l = rem & 31;
        int c_ = l & 3, nn = 8 * j + (l >> 2);
        int k0 = 8 * s + c_;
        unsigned v0 = f2tf(__ldg(W + k0 * KOUT + nn));
        unsigned v1 = f2tf(__ldg(W + (k0 + 4) * KOUT + nn));
        bsm[i] = make_uint2(v0, v1);
    }
    float* epiA = smw + 8192;
    float* epiB = smw + 8192 + KOUT;
    if constexpr (EPI) {
        for (int cix = threadIdx.x; cix < KOUT; cix += NTHR) {
            float Av = __ldg(gam + cix) * rsqrtf(__ldg(var + cix) + EPS);
            epiA[cix] = Av;
            epiB[cix] = __ldg(bet + cix) + (__ldg(bias + cix) - __ldg(mu + cix)) * Av;
        }
    }
    __syncthreads();

    int nrt = (n + 15) >> 4;
    int c = lane & 3, q = lane >> 2;
    for (int T = gw; T < nrt * CHUNKS; T += GW) {
        int rt = (CHUNKS == 1) ? T : (T / CHUNKS);
        int ch = (CHUNKS == 1) ? 0 : (T - rt * CHUNKS);
        int r0 = rt * 16 + q;
        int r1 = r0 + 8;
        int rA = r0 < n ? r0 : n - 1;
        int rB = r1 < n ? r1 : n - 1;
        const float* arow0 = A + (size_t)rA * KIN;
        const float* arow1 = A + (size_t)rB * KIN;
        float acc[JT][4];
#pragma unroll
        for (int jj = 0; jj < JT; jj++) {
            acc[jj][0] = 0.f; acc[jj][1] = 0.f; acc[jj][2] = 0.f; acc[jj][3] = 0.f;
        }
#pragma unroll
        for (int s = 0; s < KS; s++) {
            unsigned a0 = f2tf(__ldg(arow0 + 8 * s + c));
            unsigned a1 = f2tf(__ldg(arow1 + 8 * s + c));
            unsigned a2 = f2tf(__ldg(arow0 + 8 * s + 4 + c));
            unsigned a3 = f2tf(__ldg(arow1 + 8 * s + 4 + c));
#pragma unroll
            for (int jj = 0; jj < JT; jj++) {
                uint2 bb = bsm[((ch * JT + jj) * KS + s) * 32 + lane];
                mma1688(acc[jj], a0, a1, a2, a3, bb.x, bb.y);
            }
        }
#pragma unroll
        for (int jj = 0; jj < JT; jj++) {
            int col0 = 8 * (ch * JT + jj) + 2 * c;
            float x0 = acc[jj][0], x1 = acc[jj][1], x2 = acc[jj][2], x3 = acc[jj][3];
            if constexpr (EPI) {
                float A0 = epiA[col0], B0 = epiB[col0];
                float A1 = epiA[col0 + 1], B1 = epiB[col0 + 1];
                x0 = fmaxf(x0 * A0 + B0, 0.f); x1 = fmaxf(x1 * A1 + B1, 0.f);
                x2 = fmaxf(x2 * A0 + B0, 0.f); x3 = fmaxf(x3 * A1 + B1, 0.f);
            }
            if constexpr (BOUT) {
                int ci = col0 >> 1;
                if (r0 < n) Cb[(size_t)r0 * KOUT2 + ci] = f2bf(x0, x1);
                if (r1 < n) Cb[(size_t)r1 * KOUT2 + ci] = f2bf(x2, x3);
            } else {
                if (r0 < n)
                    *reinterpret_cast<float2*>(Cf + (size_t)r0 * KOUT + col0) = make_float2(x0, x1);
                if (r1 < n)
                    *reinterpret_cast<float2*>(Cf + (size_t)r1 * KOUT + col0) = make_float2(x2, x3);
            }
        }
    }
}

// ---------------- GCN aggregation (D=64) from bf16, fp32 out ----------------
template <bool EPIL>
__device__ void stage_agg64(const unsigned* __restrict__ featb, float* __restrict__ out, int n,
                            int lane, int gw, int GW,
                            const float* __restrict__ bias, const float* __restrict__ gam,
                            const float* __restrict__ bet, const float* __restrict__ mu,
                            const float* __restrict__ var) {
    constexpr int PR = 32;
    int li = lane;
    float A0 = 1.f, A1 = 1.f, B0 = 0.f, B1 = 0.f;
    if constexpr (EPIL) {
        int d0 = 2 * li, d1 = 2 * li + 1;
        A0 = __ldg(gam + d0) * rsqrtf(__ldg(var + d0) + EPS);
        B0 = __ldg(bet + d0) + (__ldg(bias + d0) - __ldg(mu + d0)) * A0;
        A1 = __ldg(gam + d1) * rsqrtf(__ldg(var + d1) + EPS);
        B1 = __ldg(bet + d1) + (__ldg(bias + d1) - __ldg(mu + d1)) * A1;
    }
    for (int w = gw; w < n; w += GW) {
        float di = g_dinv[w];
        int cnt = g_deg[w];
        const int* __restrict__ pl = g_perm + (size_t)w * SLOTS;
        float ax, ay;
        {
            float nm = di * di;
            float2 v = bf2f(__ldg(featb + (size_t)w * PR + li));
            ax = nm * v.x; ay = nm * v.y;
        }
        int e = 0;
        for (; e + 8 <= cnt; e += 8) {
            int s[8]; float nm[8]; unsigned r[8];
#pragma unroll
            for (int u = 0; u < 8; u++) s[u] = __ldg(pl + e + u);
#pragma unroll
            for (int u = 0; u < 8; u++) r[u] = __ldg(featb + (size_t)s[u] * PR + li);
#pragma unroll
            for (int u = 0; u < 8; u++) nm[u] = di * __ldg(g_dinv + s[u]);
#pragma unroll
            for (int u = 0; u < 8; u++) {
                float2 v = bf2f(r[u]);
                ax += nm[u] * v.x; ay += nm[u] * v.y;
            }
        }
        for (; e + 4 <= cnt; e += 4) {
            int s[4]; float nm[4]; unsigned r[4];
#pragma unroll
            for (int u = 0; u < 4; u++) s[u] = __ldg(pl + e + u);
#pragma unroll
            for (int u = 0; u < 4; u++) r[u] = __ldg(featb + (size_t)s[u] * PR + li);
#pragma unroll
            for (int u = 0; u < 4; u++) nm[u] = di * __ldg(g_dinv + s[u]);
#pragma unroll
            for (int u = 0; u < 4; u++) {
                float2 v = bf2f(r[u]);
                ax += nm[u] * v.x; ay += nm[u] * v.y;
            }
        }
        for (; e < cnt; e++) {
            int sn = __ldg(pl + e);
            float nm = di * __ldg(g_dinv + sn);
            float2 v = bf2f(__ldg(featb + (size_t)sn * PR + li));
            ax += nm * v.x; ay += nm * v.y;
        }
        if constexpr (EPIL) {
            ax = fmaxf(ax * A0 + B0, 0.f);
            ay = fmaxf(ay * A1 + B1, 0.f);
        }
        *reinterpret_cast<float2*>(out + (size_t)w * 64 + li * 2) = make_float2(ax, ay);
    }
}

// ---------------- GCN aggregation (D=32), two nodes per warp, fp32 out + epilogue ----------------
__device__ void stage_agg32_dual(const unsigned* __restrict__ featb, float* __restrict__ out, int n,
                                 int lane, int gw, int GW,
                                 const float* __restrict__ bias, const float* __restrict__ gam,
                                 const float* __restrict__ bet, const float* __restrict__ mu,
                                 const float* __restrict__ var) {
    int sub = lane >> 4;
    int li = lane & 15;
    int d0 = 2 * li, d1 = 2 * li + 1;
    float A0 = __ldg(gam + d0) * rsqrtf(__ldg(var + d0) + EPS);
    float B0 = __ldg(bet + d0) + (__ldg(bias + d0) - __ldg(mu + d0)) * A0;
    float A1 = __ldg(gam + d1) * rsqrtf(__ldg(var + d1) + EPS);
    float B1 = __ldg(bet + d1) + (__ldg(bias + d1) - __ldg(mu + d1)) * A1;

    for (int base = gw * 2; base < n; base += GW * 2) {
        int w = base + sub;
        bool valid = w < n;
        int wc = valid ? w : n - 1;
        float di = g_dinv[wc];
        int cnt = g_deg[wc];
        int cnto = __shfl_xor_sync(0xffffffffu, cnt, 16);
        int cmax = cnt > cnto ? cnt : cnto;
        const int* __restrict__ pl = g_perm + (size_t)wc * SLOTS;
        float ax, ay;
        {
            float nm = di * di;
            float2 v = bf2f(__ldg(featb + (size_t)wc * 16 + li));
            ax = nm * v.x; ay = nm * v.y;
        }
        int e = 0;
        for (; e + 4 <= cmax; e += 4) {
            int s[4]; float nm[4]; unsigned r[4];
#pragma unroll
            for (int u = 0; u < 4; u++) {
                bool a = (e + u) < cnt;
                s[u] = a ? __ldg(pl + e + u) : wc;
                nm[u] = a ? 1.f : 0.f;
            }
#pragma unroll
            for (int u = 0; u < 4; u++) r[u] = __ldg(featb + (size_t)s[u] * 16 + li);
#pragma unroll
            for (int u = 0; u < 4; u++) nm[u] *= di * __ldg(g_dinv + s[u]);
#pragma unroll
            for (int u = 0; u < 4; u++) {
                float2 v = bf2f(r[u]);
                ax += nm[u] * v.x; ay += nm[u] * v.y;
            }
        }
        for (; e < cmax; e++) {
            bool a = e < cnt;
            int sn = a ? __ldg(pl + e) : wc;
            float nm = a ? di * __ldg(g_dinv + sn) : 0.f;
            float2 v = bf2f(__ldg(featb + (size_t)sn * 16 + li));
            ax += nm * v.x; ay += nm * v.y;
        }
        ax = fmaxf(ax * A0 + B0, 0.f);
        ay = fmaxf(ay * A1 + B1, 0.f);
        if (valid)
            *reinterpret_cast<float2*>(out + (size_t)w * 32 + li * 2) = make_float2(ax, ay);
    }
}

// ---------------- the megakernel ----------------
__global__ void __launch_bounds__(NTHR, 4)
k_mega(const float* __restrict__ x, const int* __restrict__ src, const int* __restrict__ dst,
       const int* __restrict__ batch, int n, int E, int G,
       const float* W1, const float* b1, const float* g1, const float* be1, const float* m1, const float* v1,
       const float* W2, const float* b2, const float* g2, const float* be2, const float* m2, const float* v2,
       const float* W3, const float* b3, const float* g3, const float* be3, const float* m3, const float* v3,
       const float* Wg, const float* ags, const float* agd, const float* bg,
       const float* Wc1, const float* bc1, const float* Wc2, const float* bc2,
       float* __restrict__ out) {
    int tid = threadIdx.x;
    int lane = tid & 31;
    int gt = blockIdx.x * NTHR + tid;
    int gw = gt >> 5;
    const int GT = NBLK * NTHR;
    const int GW = GT / 32;

    // S0: zero cursors/pool/cnt + convert x -> bf16
    for (int i = gt; i < n; i += GT) g_cursor[i] = 0;
    if (gt < GMAX * 32) g_pool[gt] = 0.f;
    if (gt < GMAX) g_cnt[gt] = 0.f;
    for (int i = gt; i < n * 32; i += GT)
        g_xbf[i] = f2bf(__ldg(x + 2 * i), __ldg(x + 2 * i + 1));
    gridbar();

    // S1: bucket scatter by dst
    for (int e = gt; e < E; e += GT) {
        int d = dst[e];
        int slot = atomicAdd(&g_cursor[d], 1);
        if (slot < SLOTS) g_perm[(size_t)d * SLOTS + slot] = src[e];
    }
    gridbar();

    // S2: finalize degree / dinv
    for (int i = gt; i < n; i += GT) {
        int c = g_cursor[i];
        if (c > SLOTS) c = SLOTS;
        g_deg[i] = c;
        g_dinv[i] = rsqrtf((float)(c + 1));
    }
    gridbar();

    // S3: aggregate bf16 input (linearity), fp32 out
    stage_agg64<false>(g_xbf, g_bufA, n, lane, gw, GW, nullptr, nullptr, nullptr, nullptr, nullptr);
    gridbar();

    // S4: tf32 GEMM 64->128 + bias/BN/relu, fp32 out
    stage_mma<64, 128, true, false>(g_bufA, g_bufB, nullptr, W1, n, lane, gw, GW, b1, g1, be1, m1, v1);
    gridbar();

    // S5: tf32 GEMM 128->64, bf16 out
    stage_mma<128, 64, false, true>(g_bufB, nullptr, g_hh, W2, n, lane, gw, GW, nullptr, nullptr, nullptr, nullptr, nullptr);
    gridbar();

    // S6: aggregate bf16 + bias/BN/relu, fp32 out
    stage_agg64<true>(g_hh, g_bufA, n, lane, gw, GW, b2, g2, be2, m2, v2);
    gridbar();

    // S7: tf32 GEMM 64->32, bf16 out
    stage_mma<64, 32, false, true>(g_bufA, nullptr, g_xbf, W3, n, lane, gw, GW, nullptr, nullptr, nullptr, nullptr, nullptr);
    gridbar();

    // S8: aggregate bf16 + bias/BN/relu, fp32 out (32-dim), two nodes/warp
    stage_agg32_dual(g_xbf, g_bufB, n, lane, gw, GW, b3, g3, be3, m3, v3);
    gridbar();

    // S9: tf32 GEMM 32->128 (GAT projection), fp32 out
    stage_mma<32, 128, false, false>(g_bufB, g_bufA, nullptr, Wg, n, lane, gw, GW, nullptr, nullptr, nullptr, nullptr, nullptr);
    gridbar();

    // S10: attention coefficients + bf16 copy of hh — warp per node, coalesced
    {
        const float4* ags4 = reinterpret_cast<const float4*>(ags);
        const float4* agd4 = reinterpret_cast<const float4*>(agd);
        float4 sg = __ldg(ags4 + lane);   // = ags[(lane>>3)*32 + (lane&7)*4 ..]
        float4 dg = __ldg(agd4 + lane);
        for (int node = gw; node < n; node += GW) {
            float4 v = __ldg(reinterpret_cast<const float4*>(g_bufA + (size_t)node * 128) + lane);
            unsigned p0 = f2bf(v.x, v.y), p1 = f2bf(v.z, v.w);
            *reinterpret_cast<uint2*>(g_hh + (size_t)node * 64 + lane * 2) = make_uint2(p0, p1);
            float s = v.x * sg.x + v.y * sg.y + v.z * sg.z + v.w * sg.w;
            float d = v.x * dg.x + v.y * dg.y + v.z * dg.z + v.w * dg.w;
#pragma unroll
            for (int off = 4; off; off >>= 1) {
                s += __shfl_xor_sync(0xffffffffu, s, off);
                d += __shfl_xor_sync(0xffffffffu, d, off);
            }
            if ((lane & 7) == 0) {
                int h = lane >> 3;
                g_as[node * 4 + h] = s;
                g_ad[node * 4 + h] = d;
            }
        }
    }
    gridbar();

    // S11: GAT aggregation (bf16 gather) + bias/relu + fused pool
    {
        const uint2* hb = reinterpret_cast<const uint2*>(g_hh);
        int myh = lane >> 3;
        for (int nId = gw; nId < n; nId += GW) {
            const int* __restrict__ pl = g_perm + (size_t)nId * SLOTS;
            int cnt = g_deg[nId];
            float adn0 = __ldg(&g_ad[nId * 4 + 0]);
            float adn1 = __ldg(&g_ad[nId * 4 + 1]);
            float adn2 = __ldg(&g_ad[nId * 4 + 2]);
            float adn3 = __ldg(&g_ad[nId * 4 + 3]);

            float m0 = -CUDART_INF_F, m1_ = -CUDART_INF_F, m2_ = -CUDART_INF_F, m3_ = -CUDART_INF_F;
            for (int e = lane; e <= cnt; e += 32) {
                int sn = (e < cnt) ? __ldg(pl + e) : nId;
                float4 v = __ldg(reinterpret_cast<const float4*>(g_as) + sn);
                m0  = fmaxf(m0,  v.x + adn0);
                m1_ = fmaxf(m1_, v.y + adn1);
                m2_ = fmaxf(m2_, v.z + adn2);
                m3_ = fmaxf(m3_, v.w + adn3);
            }
#pragma unroll
            for (int off = 16; off; off >>= 1) {
                m0  = fmaxf(m0,  __shfl_xor_sync(0xffffffffu, m0, off));
                m1_ = fmaxf(m1_, __shfl_xor_sync(0xffffffffu, m1_, off));
                m2_ = fmaxf(m2_, __shfl_xor_sync(0xffffffffu, m2_, off));
                m3_ = fmaxf(m3_, __shfl_xor_sync(0xffffffffu, m3_, off));
            }
            float mx  = lrelu((myh == 0) ? m0 : (myh == 1) ? m1_ : (myh == 2) ? m2_ : m3_);
            float adn = (myh == 0) ? adn0 : (myh == 1) ? adn1 : (myh == 2) ? adn2 : adn3;

            float4 acc = make_float4(0.f, 0.f, 0.f, 0.f);
            float den = 0.f;
            int e = 0;
            for (; e + 4 <= cnt; e += 4) {
                int s0 = __ldg(pl + e + 0), s1 = __ldg(pl + e + 1);
                int s2 = __ldg(pl + e + 2), s3 = __ldg(pl + e + 3);
                uint2 r0 = __ldg(hb + (size_t)s0 * 32 + lane);
                uint2 r1 = __ldg(hb + (size_t)s1 * 32 + lane);
                uint2 r2 = __ldg(hb + (size_t)s2 * 32 + lane);
                uint2 r3 = __ldg(hb + (size_t)s3 * 32 + lane);
                float w0 = __expf(lrelu(__ldg(&g_as[s0 * 4 + myh]) + adn) - mx);
                float w1 = __expf(lrelu(__ldg(&g_as[s1 * 4 + myh]) + adn) - mx);
                float w2 = __expf(lrelu(__ldg(&g_as[s2 * 4 + myh]) + adn) - mx);
                float w3 = __expf(lrelu(__ldg(&g_as[s3 * 4 + myh]) + adn) - mx);
                den += (w0 + w1) + (w2 + w3);
                float2 a0 = bf2f(r0.x), b0 = bf2f(r0.y);
                float2 a1 = bf2f(r1.x), b1 = bf2f(r1.y);
                float2 a2 = bf2f(r2.x), b2 = bf2f(r2.y);
                float2 a3 = bf2f(r3.x), b3 = bf2f(r3.y);
                acc.x += w0 * a0.x + w1 * a1.x + w2 * a2.x + w3 * a3.x;
                acc.y += w0 * a0.y + w1 * a1.y + w2 * a2.y + w3 * a3.y;
                acc.z += w0 * b0.x + w1 * b1.x + w2 * b2.x + w3 * b3.x;
                acc.w += w0 * b0.y + w1 * b1.y + w2 * b2.y + w3 * b3.y;
            }
            for (; e <= cnt; e++) {
                int sn = (e < cnt) ? __ldg(pl + e) : nId;
                float w = __expf(lrelu(__ldg(&g_as[sn * 4 + myh]) + adn) - mx);
                den += w;
                uint2 r = __ldg(hb + (size_t)sn * 32 + lane);
                float2 a = bf2f(r.x), b = bf2f(r.y);
                acc.x += w * a.x; acc.y += w * a.y; acc.z += w * b.x; acc.w += w * b.y;
            }
            float inv = 1.f / den;
            acc.x *= inv; acc.y *= inv; acc.z *= inv; acc.w *= inv;
#pragma unroll
            for (int off = 8; off <= 16; off <<= 1) {
                acc.x += __shfl_xor_sync(0xffffffffu, acc.x, off);
                acc.y += __shfl_xor_sync(0xffffffffu, acc.y, off);
                acc.z += __shfl_xor_sync(0xffffffffu, acc.z, off);
                acc.w += __shfl_xor_sync(0xffffffffu, acc.w, off);
            }
            if (lane < 8) {
                float4 bgv = __ldg(reinterpret_cast<const float4*>(bg) + lane);
                int b = __ldg(batch + nId);
                float* p = &g_pool[b * 32 + lane * 4];
                atomicAdd(p + 0, fmaxf(acc.x * 0.25f + bgv.x, 0.f));
                atomicAdd(p + 1, fmaxf(acc.y * 0.25f + bgv.y, 0.f));
                atomicAdd(p + 2, fmaxf(acc.z * 0.25f + bgv.z, 0.f));
                atomicAdd(p + 3, fmaxf(acc.w * 0.25f + bgv.w, 0.f));
                if (lane == 0) atomicAdd(&g_cnt[b], 1.f);
            }
        }
    }
    gridbar();

    // S12: classifier head (block 0 only)
    if (blockIdx.x == 0) {
        float* pooled = smw;
        float* hid = smw + GMAX * 32;
        for (int t = tid; t < G * 32; t += NTHR) pooled[t] = g_pool[t] / fmaxf(g_cnt[t >> 5], 1.f);
        __syncthreads();
        for (int t = tid; t < G * 16; t += NTHR) {
            int g = t >> 4, j = t & 15;
            float s = __ldg(bc1 + j);
            for (int k = 0; k < 32; k++) s += pooled[g * 32 + k] * __ldg(Wc1 + k * 16 + j);
            hid[t] = fmaxf(s, 0.f);
        }
        __syncthreads();
        for (int t = tid; t < G * 5; t += NTHR) {
            int g = t / 5, c = t % 5;
            float s = __ldg(bc2 + c);
            for (int k = 0; k < 16; k++) s += hid[g * 16 + k] * __ldg(Wc2 + k * 5 + c);
            out[t] = s;
        }
    }
}

// ---------------- host ----------------
extern "C" void kernel_launch(void* const* d_in, const int* in_sizes, int n_in,
                              void* d_out, int out_size) {
    const float* x = (const float*)d_in[0];
    const int* ei = (const int*)d_in[1];
    const int* batch = (const int*)d_in[2];
    int n = in_sizes[0] / 64;
    int E = in_sizes[1] / 2;
    int G = out_size / 5;

    const float *W1, *b1, *W2, *b2, *W3, *b3;
    const float *g1, *be1, *m1, *v1, *g2, *be2, *m2, *v2, *g3, *be3, *m3, *v3;
    const float *Wg, *ags, *agd, *bg, *Wc1, *bc1, *Wc2, *bc2;

    if (in_sizes[5] == 128 * 64) {
        W1 = (const float*)d_in[3];  b1 = (const float*)d_in[4];
        W2 = (const float*)d_in[5];  b2 = (const float*)d_in[6];
        W3 = (const float*)d_in[7];  b3 = (const float*)d_in[8];
        g1 = (const float*)d_in[9];  be1 = (const float*)d_in[10];
        m1 = (const float*)d_in[11]; v1 = (const float*)d_in[12];
        g2 = (const float*)d_in[13]; be2 = (const float*)d_in[14];
        m2 = (const float*)d_in[15]; v2 = (const float*)d_in[16];
        g3 = (const float*)d_in[17]; be3 = (const float*)d_in[18];
        m3 = (const float*)d_in[19]; v3 = (const float*)d_in[20];
        Wg = (const float*)d_in[21]; ags = (const float*)d_in[22];
        agd = (const float*)d_in[23]; bg = (const float*)d_in[24];
        Wc1 = (const float*)d_in[25]; bc1 = (const float*)d_in[26];
        Wc2 = (const float*)d_in[27]; bc2 = (const float*)d_in[28];
    } else {
        W1 = (const float*)d_in[3];  b1 = (const float*)d_in[4];
        g1 = (const float*)d_in[5];  be1 = (const float*)d_in[6];
        m1 = (const float*)d_in[7];  v1 = (const float*)d_in[8];
        W2 = (const float*)d_in[9];  b2 = (const float*)d_in[10];
        g2 = (const float*)d_in[11]; be2 = (const float*)d_in[12];
        m2 = (const float*)d_in[13]; v2 = (const float*)d_in[14];
        W3 = (const float*)d_in[15]; b3 = (const float*)d_in[16];
        g3 = (const float*)d_in[17]; be3 = (const float*)d_in[18];
        m3 = (const float*)d_in[19]; v3 = (const float*)d_in[20];
        Wg = (const float*)d_in[21]; ags = (const float*)d_in[22];
        agd = (const float*)d_in[23]; bg = (const float*)d_in[24];
        Wc1 = (const float*)d_in[25]; bc1 = (const float*)d_in[26];
        Wc2 = (const float*)d_in[27]; bc2 = (const float*)d_in[28];
    }

    const int* src = ei;
    const int* dst = ei + E;

    k_mega<<<NBLK, NTHR>>>(x, src, dst, batch, n, E, G,
                           W1, b1, g1, be1, m1, v1,
                           W2, b2, g2, be2, m2, v2,
                           W3, b3, g3, be3, m3, v3,
                           Wg, ags, agd, bg,
                           Wc1, bc1, Wc2, bc2,
                           (float*)d_out);
}

// round 10
// speedup vs baseline: 1.6113x; 1.0697x over previous
#include <cuda_runtime.h>
#include <cuda_bf16.h>
#include <math_constants.h>

#define NMAX 100000
#define GMAX 64
#define SLOTS 64
#define EPS 1e-5f
#define NEG_SLOPE 0.2f
#define NBLK 592          // 148 SMs x 4 blocks, all co-resident
#define NTHR 256

// ---------------- scratch (device globals) ----------------
__device__ __align__(16) unsigned g_B128[NMAX * 64];  // bf16x2, 128 cols/node
__device__ __align__(16) unsigned g_B64a[NMAX * 32];  // bf16x2, up to 64 cols/node
__device__ __align__(16) unsigned g_B64b[NMAX * 32];
__device__ float g_dinv[NMAX];
__device__ int   g_deg[NMAX];
__device__ int   g_cursor[NMAX];
__device__ int   g_perm[NMAX * SLOTS];
__device__ __align__(16) float g_as[NMAX * 4];
__device__ __align__(16) float g_ad[NMAX * 4];
__device__ float g_pool[GMAX * 32];
__device__ float g_cnt[GMAX];
__device__ unsigned g_gmaxu[4];
__device__ unsigned g_gen  = 0;
__device__ unsigned g_bcnt = 0;

// ---------------- grid-wide barrier (volatile-load polling, no atomic spin) ----------------
__device__ __forceinline__ void gridbar() {
    __syncthreads();
    if (threadIdx.x == 0) {
        unsigned my = *(volatile unsigned*)&g_gen;
        __threadfence();
        if (atomicAdd(&g_bcnt, 1u) == NBLK - 1u) {
            atomicExch(&g_bcnt, 0u);
            __threadfence();
            atomicAdd(&g_gen, 1u);
        } else {
            while (*(volatile unsigned*)&g_gen == my) __nanosleep(64);
        }
        __threadfence();
    }
    __syncthreads();
}

__device__ __forceinline__ float lrelu(float x) { return x > 0.f ? x : NEG_SLOPE * x; }
__device__ __forceinline__ float2 bf2f(unsigned u) {
    return __bfloat1622float2(*reinterpret_cast<const __nv_bfloat162*>(&u));
}
__device__ __forceinline__ unsigned f2bf(float a, float b) {
    __nv_bfloat162 p = __floats2bfloat162_rn(a, b);
    return *reinterpret_cast<unsigned*>(&p);
}
__device__ __forceinline__ unsigned f2tf(float f) {
    unsigned u;
    asm("cvt.rna.tf32.f32 %0, %1;" : "=r"(u) : "f"(f));
    return u;
}
// order-preserving float<->unsigned for atomicMax
__device__ __forceinline__ unsigned fenc(float f) {
    int b = __float_as_int(f);
    return (b >= 0) ? ((unsigned)b | 0x80000000u) : (unsigned)(~b);
}
__device__ __forceinline__ float fdec(unsigned k) {
    return (k & 0x80000000u) ? __int_as_float((int)(k & 0x7FFFFFFFu))
                             : __int_as_float((int)~k);
}

__shared__ __align__(16) float smw[10240];   // 40KB stage scratch

// ---------------- tensor-core MMA m16n8k8 tf32 -> fp32 ----------------
__device__ __forceinline__ void mma1688(float c[4], unsigned a0, unsigned a1,
                                        unsigned a2, unsigned a3, unsigned b0, unsigned b1) {
    asm volatile(
        "mma.sync.aligned.m16n8k8.row.col.f32.tf32.tf32.f32 "
        "{%0,%1,%2,%3}, {%4,%5,%6,%7}, {%8,%9}, {%0,%1,%2,%3};"
        : "+f"(c[0]), "+f"(c[1]), "+f"(c[2]), "+f"(c[3])
        : "r"(a0), "r"(a1), "r"(a2), "r"(a3), "r"(b0), "r"(b1));
}

// ---------------- GEMM via tf32 MMA: A bf16 -> C bf16, opt bias+BN+relu ----------------
// bf16 A halves are expanded to f32 bit patterns (<<16 / mask) = exact tf32 operands.
template <int KIN, int KOUT, bool EPI>
__device__ void stage_mma(const unsigned* __restrict__ Ab, unsigned* __restrict__ Cb,
                          const float* __restrict__ W, int n, int lane, int gw, int GW,
                          const float* __restrict__ bias, const float* __restrict__ gam,
                          const float* __restrict__ bet, const float* __restrict__ mu,
                          const float* __restrict__ var) {
    constexpr int KS = KIN / 8;
    constexpr int NT = KOUT / 8;
    constexpr int JT = (NT >= 8) ? 8 : NT;
    constexpr int CHUNKS = NT / JT;
    constexpr int KIN2 = KIN / 2;
    constexpr int KOUT2 = KOUT / 2;

    uint2* bsm = reinterpret_cast<uint2*>(smw);   // fragment-ordered tf32 weights
    for (int i = threadIdx.x; i < NT * KS * 32; i += NTHR) {
        int j = i / (KS * 32);
        int rem = i - j * (KS * 32);
        int s = rem >> 5;
        int l = rem & 31;
        int c_ = l & 3, nn = 8 * j + (l >> 2);
        int k0 = 8 * s + c_;
        unsigned v0 = f2tf(__ldg(W + k0 * KOUT + nn));
        unsigned v1 = f2tf(__ldg(W + (k0 + 4) * KOUT + nn));
        bsm[i] = make_uint2(v0, v1);
    }
    float* epiA = smw + 8192;
    float* epiB = smw + 8192 + KOUT;
    if constexpr (EPI) {
        for (int cix = threadIdx.x; cix < KOUT; cix += NTHR) {
            float Av = __ldg(gam + cix) * rsqrtf(__ldg(var + cix) + EPS);
            epiA[cix] = Av;
            epiB[cix] = __ldg(bet + cix) + (__ldg(bias + cix) - __ldg(mu + cix)) * Av;
        }
    }
    __syncthreads();

    int nrt = (n + 15) >> 4;
    int c = lane & 3, q = lane >> 2;
    int hw = c >> 1;               // word offset within 4-word k-group
    bool hi = (c & 1);             // which bf16 half
    for (int T = gw; T < nrt * CHUNKS; T += GW) {
        int rt = (CHUNKS == 1) ? T : (T / CHUNKS);
        int ch = (CHUNKS == 1) ? 0 : (T - rt * CHUNKS);
        int r0 = rt * 16 + q;
        int r1 = r0 + 8;
        int rA = r0 < n ? r0 : n - 1;
        int rB = r1 < n ? r1 : n - 1;
        const unsigned* arow0 = Ab + (size_t)rA * KIN2;
        const unsigned* arow1 = Ab + (size_t)rB * KIN2;
        float acc[JT][4];
#pragma unroll
        for (int jj = 0; jj < JT; jj++) {
            acc[jj][0] = 0.f; acc[jj][1] = 0.f; acc[jj][2] = 0.f; acc[jj][3] = 0.f;
        }
#pragma unroll
        for (int s = 0; s < KS; s++) {
            unsigned wa0 = __ldg(arow0 + 4 * s + hw);
            unsigned wa1 = __ldg(arow0 + 4 * s + 2 + hw);
            unsigned wb0 = __ldg(arow1 + 4 * s + hw);
            unsigned wb1 = __ldg(arow1 + 4 * s + 2 + hw);
            unsigned a0 = hi ? (wa0 & 0xFFFF0000u) : (wa0 << 16);
            unsigned a2 = hi ? (wa1 & 0xFFFF0000u) : (wa1 << 16);
            unsigned a1 = hi ? (wb0 & 0xFFFF0000u) : (wb0 << 16);
            unsigned a3 = hi ? (wb1 & 0xFFFF0000u) : (wb1 << 16);
#pragma unroll
            for (int jj = 0; jj < JT; jj++) {
                uint2 bb = bsm[((ch * JT + jj) * KS + s) * 32 + lane];
                mma1688(acc[jj], a0, a1, a2, a3, bb.x, bb.y);
            }
        }
#pragma unroll
        for (int jj = 0; jj < JT; jj++) {
            int col0 = 8 * (ch * JT + jj) + 2 * c;
            float x0 = acc[jj][0], x1 = acc[jj][1], x2 = acc[jj][2], x3 = acc[jj][3];
            if constexpr (EPI) {
                float A0 = epiA[col0], B0 = epiB[col0];
                float A1 = epiA[col0 + 1], B1 = epiB[col0 + 1];
                x0 = fmaxf(x0 * A0 + B0, 0.f); x1 = fmaxf(x1 * A1 + B1, 0.f);
                x2 = fmaxf(x2 * A0 + B0, 0.f); x3 = fmaxf(x3 * A1 + B1, 0.f);
            }
            int ci = col0 >> 1;
            if (r0 < n) Cb[(size_t)r0 * KOUT2 + ci] = f2bf(x0, x1);
            if (r1 < n) Cb[(size_t)r1 * KOUT2 + ci] = f2bf(x2, x3);
        }
    }
}

// ---------------- GCN aggregation (D=64) bf16 -> bf16, opt bias+BN+relu ----------------
template <bool EPIL>
__device__ void stage_agg64(const unsigned* __restrict__ featb, unsigned* __restrict__ outb, int n,
                            int lane, int gw, int GW,
                            const float* __restrict__ bias, const float* __restrict__ gam,
                            const float* __restrict__ bet, const float* __restrict__ mu,
                            const float* __restrict__ var) {
    constexpr int PR = 32;
    int li = lane;
    float A0 = 1.f, A1 = 1.f, B0 = 0.f, B1 = 0.f;
    if constexpr (EPIL) {
        int d0 = 2 * li, d1 = 2 * li + 1;
        A0 = __ldg(gam + d0) * rsqrtf(__ldg(var + d0) + EPS);
        B0 = __ldg(bet + d0) + (__ldg(bias + d0) - __ldg(mu + d0)) * A0;
        A1 = __ldg(gam + d1) * rsqrtf(__ldg(var + d1) + EPS);
        B1 = __ldg(bet + d1) + (__ldg(bias + d1) - __ldg(mu + d1)) * A1;
    }
    for (int w = gw; w < n; w += GW) {
        float di = g_dinv[w];
        int cnt = g_deg[w];
        const int* __restrict__ pl = g_perm + (size_t)w * SLOTS;
        float ax, ay;
        {
            float nm = di * di;
            float2 v = bf2f(__ldg(featb + (size_t)w * PR + li));
            ax = nm * v.x; ay = nm * v.y;
        }
        int e = 0;
        for (; e + 8 <= cnt; e += 8) {
            int s[8]; float nm[8]; unsigned r[8];
#pragma unroll
            for (int u = 0; u < 8; u++) s[u] = __ldg(pl + e + u);
#pragma unroll
            for (int u = 0; u < 8; u++) r[u] = __ldg(featb + (size_t)s[u] * PR + li);
#pragma unroll
            for (int u = 0; u < 8; u++) nm[u] = di * __ldg(g_dinv + s[u]);
#pragma unroll
            for (int u = 0; u < 8; u++) {
                float2 v = bf2f(r[u]);
                ax += nm[u] * v.x; ay += nm[u] * v.y;
            }
        }
        for (; e + 4 <= cnt; e += 4) {
            int s[4]; float nm[4]; unsigned r[4];
#pragma unroll
            for (int u = 0; u < 4; u++) s[u] = __ldg(pl + e + u);
#pragma unroll
            for (int u = 0; u < 4; u++) r[u] = __ldg(featb + (size_t)s[u] * PR + li);
#pragma unroll
            for (int u = 0; u < 4; u++) nm[u] = di * __ldg(g_dinv + s[u]);
#pragma unroll
            for (int u = 0; u < 4; u++) {
                float2 v = bf2f(r[u]);
                ax += nm[u] * v.x; ay += nm[u] * v.y;
            }
        }
        for (; e < cnt; e++) {
            int sn = __ldg(pl + e);
            float nm = di * __ldg(g_dinv + sn);
            float2 v = bf2f(__ldg(featb + (size_t)sn * PR + li));
            ax += nm * v.x; ay += nm * v.y;
        }
        if constexpr (EPIL) {
            ax = fmaxf(ax * A0 + B0, 0.f);
            ay = fmaxf(ay * A1 + B1, 0.f);
        }
        outb[(size_t)w * PR + li] = f2bf(ax, ay);
    }
}

// ---------------- GCN aggregation (D=32), two nodes per warp, bf16 out + epilogue ----------------
__device__ void stage_agg32_dual(const unsigned* __restrict__ featb, unsigned* __restrict__ outb, int n,
                                 int lane, int gw, int GW,
                                 const float* __restrict__ bias, const float* __restrict__ gam,
                                 const float* __restrict__ bet, const float* __restrict__ mu,
                                 const float* __restrict__ var) {
    int sub = lane >> 4;
    int li = lane & 15;
    int d0 = 2 * li, d1 = 2 * li + 1;
    float A0 = __ldg(gam + d0) * rsqrtf(__ldg(var + d0) + EPS);
    float B0 = __ldg(bet + d0) + (__ldg(bias + d0) - __ldg(mu + d0)) * A0;
    float A1 = __ldg(gam + d1) * rsqrtf(__ldg(var + d1) + EPS);
    float B1 = __ldg(bet + d1) + (__ldg(bias + d1) - __ldg(mu + d1)) * A1;

    for (int base = gw * 2; base < n; base += GW * 2) {
        int w = base + sub;
        bool valid = w < n;
        int wc = valid ? w : n - 1;
        float di = g_dinv[wc];
        int cnt = g_deg[wc];
        int cnto = __shfl_xor_sync(0xffffffffu, cnt, 16);
        int cmax = cnt > cnto ? cnt : cnto;
        const int* __restrict__ pl = g_perm + (size_t)wc * SLOTS;
        float ax, ay;
        {
            float nm = di * di;
            float2 v = bf2f(__ldg(featb + (size_t)wc * 16 + li));
            ax = nm * v.x; ay = nm * v.y;
        }
        int e = 0;
        for (; e + 4 <= cmax; e += 4) {
            int s[4]; float nm[4]; unsigned r[4];
#pragma unroll
            for (int u = 0; u < 4; u++) {
                bool a = (e + u) < cnt;
                s[u] = a ? __ldg(pl + e + u) : wc;
                nm[u] = a ? 1.f : 0.f;
            }
#pragma unroll
            for (int u = 0; u < 4; u++) r[u] = __ldg(featb + (size_t)s[u] * 16 + li);
#pragma unroll
            for (int u = 0; u < 4; u++) nm[u] *= di * __ldg(g_dinv + s[u]);
#pragma unroll
            for (int u = 0; u < 4; u++) {
                float2 v = bf2f(r[u]);
                ax += nm[u] * v.x; ay += nm[u] * v.y;
            }
        }
        for (; e < cmax; e++) {
            bool a = e < cnt;
            int sn = a ? __ldg(pl + e) : wc;
            float nm = a ? di * __ldg(g_dinv + sn) : 0.f;
            float2 v = bf2f(__ldg(featb + (size_t)sn * 16 + li));
            ax += nm * v.x; ay += nm * v.y;
        }
        ax = fmaxf(ax * A0 + B0, 0.f);
        ay = fmaxf(ay * A1 + B1, 0.f);
        if (valid) outb[(size_t)w * 16 + li] = f2bf(ax, ay);
    }
}

// ---------------- the megakernel ----------------
__global__ void __launch_bounds__(NTHR, 4)
k_mega(const float* __restrict__ x, const int* __restrict__ src, const int* __restrict__ dst,
       const int* __restrict__ batch, int n, int E, int G,
       const float* W1, const float* b1, const float* g1, const float* be1, const float* m1, const float* v1,
       const float* W2, const float* b2, const float* g2, const float* be2, const float* m2, const float* v2,
       const float* W3, const float* b3, const float* g3, const float* be3, const float* m3, const float* v3,
       const float* Wg, const float* ags, const float* agd, const float* bg,
       const float* Wc1, const float* bc1, const float* Wc2, const float* bc2,
       float* __restrict__ out) {
    int tid = threadIdx.x;
    int lane = tid & 31;
    int gt = blockIdx.x * NTHR + tid;
    int gw = gt >> 5;
    const int GT = NBLK * NTHR;
    const int GW = GT / 32;

    // S0: zero cursors/pool/cnt/gmax + convert x -> bf16 (B64a)
    for (int i = gt; i < n; i += GT) g_cursor[i] = 0;
    if (gt < GMAX * 32) g_pool[gt] = 0.f;
    if (gt < GMAX) g_cnt[gt] = 0.f;
    if (gt < 4) g_gmaxu[gt] = 0u;
    for (int i = gt; i < n * 32; i += GT)
        g_B64a[i] = f2bf(__ldg(x + 2 * i), __ldg(x + 2 * i + 1));
    gridbar();

    // S1: bucket scatter by dst
    for (int e = gt; e < E; e += GT) {
        int d = dst[e];
        int slot = atomicAdd(&g_cursor[d], 1);
        if (slot < SLOTS) g_perm[(size_t)d * SLOTS + slot] = src[e];
    }
    gridbar();

    // S2: finalize degree / dinv
    for (int i = gt; i < n; i += GT) {
        int c = g_cursor[i];
        if (c > SLOTS) c = SLOTS;
        g_deg[i] = c;
        g_dinv[i] = rsqrtf((float)(c + 1));
    }
    gridbar();

    // S3: aggregate input (linearity), bf16 -> bf16
    stage_agg64<false>(g_B64a, g_B64b, n, lane, gw, GW, nullptr, nullptr, nullptr, nullptr, nullptr);
    gridbar();

    // S4: tf32 GEMM 64->128 + bias/BN/relu
    stage_mma<64, 128, true>(g_B64b, g_B128, W1, n, lane, gw, GW, b1, g1, be1, m1, v1);
    gridbar();

    // S5: tf32 GEMM 128->64
    stage_mma<128, 64, false>(g_B128, g_B64a, W2, n, lane, gw, GW, nullptr, nullptr, nullptr, nullptr, nullptr);
    gridbar();

    // S6: aggregate + bias/BN/relu
    stage_agg64<true>(g_B64a, g_B64b, n, lane, gw, GW, b2, g2, be2, m2, v2);
    gridbar();

    // S7: tf32 GEMM 64->32
    stage_mma<64, 32, false>(g_B64b, g_B64a, W3, n, lane, gw, GW, nullptr, nullptr, nullptr, nullptr, nullptr);
    gridbar();

    // S8: aggregate + bias/BN/relu (32-dim), two nodes/warp
    stage_agg32_dual(g_B64a, g_B64b, n, lane, gw, GW, b3, g3, be3, m3, v3);
    gridbar();

    // S9: tf32 GEMM 32->128 (GAT projection), bf16 out -> B128
    stage_mma<32, 128, false>(g_B64b, g_B128, Wg, n, lane, gw, GW, nullptr, nullptr, nullptr, nullptr, nullptr);
    gridbar();

    // S10: attention coefficients from bf16 hh (no extra store) + per-head global max
    {
        unsigned* gm = reinterpret_cast<unsigned*>(smw);
        if (tid < 4) gm[tid] = 0u;
        __syncthreads();
        const float4* ags4 = reinterpret_cast<const float4*>(ags);
        const float4* agd4 = reinterpret_cast<const float4*>(agd);
        float4 sg = __ldg(ags4 + lane);
        float4 dg = __ldg(agd4 + lane);
        const uint2* hb = reinterpret_cast<const uint2*>(g_B128);
        float smax = -CUDART_INF_F;
        for (int node = gw; node < n; node += GW) {
            uint2 w = __ldg(hb + (size_t)node * 32 + lane);
            float2 p0 = bf2f(w.x), p1 = bf2f(w.y);
            float s = p0.x * sg.x + p0.y * sg.y + p1.x * sg.z + p1.y * sg.w;
            float d = p0.x * dg.x + p0.y * dg.y + p1.x * dg.z + p1.y * dg.w;
#pragma unroll
            for (int off = 4; off; off >>= 1) {
                s += __shfl_xor_sync(0xffffffffu, s, off);
                d += __shfl_xor_sync(0xffffffffu, d, off);
            }
            if ((lane & 7) == 0) {
                int h = lane >> 3;
                g_as[node * 4 + h] = s;
                g_ad[node * 4 + h] = d;
            }
            smax = fmaxf(smax, s);
        }
        if ((lane & 7) == 0) atomicMax(&gm[lane >> 3], fenc(smax));
        __syncthreads();
        if (tid < 4) atomicMax(&g_gmaxu[tid], gm[tid]);
    }
    gridbar();

    // S11: GAT aggregation (bf16 gather, global-max softmax) + bias/relu + fused pool
    {
        const uint2* hb = reinterpret_cast<const uint2*>(g_B128);
        int myh = lane >> 3;
        float gmax = fdec(g_gmaxu[myh]);   // upper bound on a_s for this head
        for (int nId = gw; nId < n; nId += GW) {
            const int* __restrict__ pl = g_perm + (size_t)nId * SLOTS;
            int cnt = g_deg[nId];
            float4 adn4 = __ldg(reinterpret_cast<const float4*>(g_ad) + nId);
            float adn = (myh == 0) ? adn4.x : (myh == 1) ? adn4.y : (myh == 2) ? adn4.z : adn4.w;
            float mx = lrelu(gmax + adn);  // >= lrelu(as[src]+adn) for every src (monotone)

            float4 acc = make_float4(0.f, 0.f, 0.f, 0.f);
            float den = 0.f;
            int e = 0;
            for (; e + 4 <= cnt; e += 4) {
                int s0 = __ldg(pl + e + 0), s1 = __ldg(pl + e + 1);
                int s2 = __ldg(pl + e + 2), s3 = __ldg(pl + e + 3);
                uint2 r0 = __ldg(hb + (size_t)s0 * 32 + lane);
                uint2 r1 = __ldg(hb + (size_t)s1 * 32 + lane);
                uint2 r2 = __ldg(hb + (size_t)s2 * 32 + lane);
                uint2 r3 = __ldg(hb + (size_t)s3 * 32 + lane);
                float w0 = __expf(lrelu(__ldg(&g_as[s0 * 4 + myh]) + adn) - mx);
                float w1 = __expf(lrelu(__ldg(&g_as[s1 * 4 + myh]) + adn) - mx);
                float w2 = __expf(lrelu(__ldg(&g_as[s2 * 4 + myh]) + adn) - mx);
                float w3 = __expf(lrelu(__ldg(&g_as[s3 * 4 + myh]) + adn) - mx);
                den += (w0 + w1) + (w2 + w3);
                float2 a0 = bf2f(r0.x), b0 = bf2f(r0.y);
                float2 a1 = bf2f(r1.x), b1 = bf2f(r1.y);
                float2 a2 = bf2f(r2.x), b2 = bf2f(r2.y);
                float2 a3 = bf2f(r3.x), b3 = bf2f(r3.y);
                acc.x += w0 * a0.x + w1 * a1.x + w2 * a2.x + w3 * a3.x;
                acc.y += w0 * a0.y + w1 * a1.y + w2 * a2.y + w3 * a3.y;
                acc.z += w0 * b0.x + w1 * b1.x + w2 * b2.x + w3 * b3.x;
                acc.w += w0 * b0.y + w1 * b1.y + w2 * b2.y + w3 * b3.y;
            }
            for (; e <= cnt; e++) {
                int sn = (e < cnt) ? __ldg(pl + e) : nId;
                float w = __expf(lrelu(__ldg(&g_as[sn * 4 + myh]) + adn) - mx);
                den += w;
                uint2 r = __ldg(hb + (size_t)sn * 32 + lane);
                float2 a = bf2f(r.x), b = bf2f(r.y);
                acc.x += w * a.x; acc.y += w * a.y; acc.z += w * b.x; acc.w += w * b.y;
            }
            float inv = 1.f / den;
            acc.x *= inv; acc.y *= inv; acc.z *= inv; acc.w *= inv;
#pragma unroll
            for (int off = 8; off <= 16; off <<= 1) {
                acc.x += __shfl_xor_sync(0xffffffffu, acc.x, off);
                acc.y += __shfl_xor_sync(0xffffffffu, acc.y, off);
                acc.z += __shfl_xor_sync(0xffffffffu, acc.z, off);
                acc.w += __shfl_xor_sync(0xffffffffu, acc.w, off);
            }
            if (lane < 8) {
                float4 bgv = __ldg(reinterpret_cast<const float4*>(bg) + lane);
                int b = __ldg(batch + nId);
                float* p = &g_pool[b * 32 + lane * 4];
                atomicAdd(p + 0, fmaxf(acc.x * 0.25f + bgv.x, 0.f));
                atomicAdd(p + 1, fmaxf(acc.y * 0.25f + bgv.y, 0.f));
                atomicAdd(p + 2, fmaxf(acc.z * 0.25f + bgv.z, 0.f));
                atomicAdd(p + 3, fmaxf(acc.w * 0.25f + bgv.w, 0.f));
                if (lane == 0) atomicAdd(&g_cnt[b], 1.f);
            }
        }
    }
    gridbar();

    // S12: classifier head (block 0 only)
    if (blockIdx.x == 0) {
        float* pooled = smw;
        float* hid = smw + GMAX * 32;
        for (int t = tid; t < G * 32; t += NTHR) pooled[t] = g_pool[t] / fmaxf(g_cnt[t >> 5], 1.f);
        __syncthreads();
        for (int t = tid; t < G * 16; t += NTHR) {
            int g = t >> 4, j = t & 15;
            float s = __ldg(bc1 + j);
            for (int k = 0; k < 32; k++) s += pooled[g * 32 + k] * __ldg(Wc1 + k * 16 + j);
            hid[t] = fmaxf(s, 0.f);
        }
        __syncthreads();
        for (int t = tid; t < G * 5; t += NTHR) {
            int g = t / 5, c = t % 5;
            float s = __ldg(bc2 + c);
            for (int k = 0; k < 16; k++) s += hid[g * 16 + k] * __ldg(Wc2 + k * 5 + c);
            out[t] = s;
        }
    }
}

// ---------------- host ----------------
extern "C" void kernel_launch(void* const* d_in, const int* in_sizes, int n_in,
                              void* d_out, int out_size) {
    const float* x = (const float*)d_in[0];
    const int* ei = (const int*)d_in[1];
    const int* batch = (const int*)d_in[2];
    int n = in_sizes[0] / 64;
    int E = in_sizes[1] / 2;
    int G = out_size / 5;

    const float *W1, *b1, *W2, *b2, *W3, *b3;
    const float *g1, *be1, *m1, *v1, *g2, *be2, *m2, *v2, *g3, *be3, *m3, *v3;
    const float *Wg, *ags, *agd, *bg, *Wc1, *bc1, *Wc2, *bc2;

    if (in_sizes[5] == 128 * 64) {
        W1 = (const float*)d_in[3];  b1 = (const float*)d_in[4];
        W2 = (const float*)d_in[5];  b2 = (const float*)d_in[6];
        W3 = (const float*)d_in[7];  b3 = (const float*)d_in[8];
        g1 = (const float*)d_in[9];  be1 = (const float*)d_in[10];
        m1 = (const float*)d_in[11]; v1 = (const float*)d_in[12];
        g2 = (const float*)d_in[13]; be2 = (const float*)d_in[14];
        m2 = (const float*)d_in[15]; v2 = (const float*)d_in[16];
        g3 = (const float*)d_in[17]; be3 = (const float*)d_in[18];
        m3 = (const float*)d_in[19]; v3 = (const float*)d_in[20];
        Wg = (const float*)d_in[21]; ags = (const float*)d_in[22];
        agd = (const float*)d_in[23]; bg = (const float*)d_in[24];
        Wc1 = (const float*)d_in[25]; bc1 = (const float*)d_in[26];
        Wc2 = (const float*)d_in[27]; bc2 = (const float*)d_in[28];
    } else {
        W1 = (const float*)d_in[3];  b1 = (const float*)d_in[4];
        g1 = (const float*)d_in[5];  be1 = (const float*)d_in[6];
        m1 = (const float*)d_in[7];  v1 = (const float*)d_in[8];
        W2 = (const float*)d_in[9];  b2 = (const float*)d_in[10];
        g2 = (const float*)d_in[11]; be2 = (const float*)d_in[12];
        m2 = (const float*)d_in[13]; v2 = (const float*)d_in[14];
        W3 = (const float*)d_in[15]; b3 = (const float*)d_in[16];
        g3 = (const float*)d_in[17]; be3 = (const float*)d_in[18];
        m3 = (const float*)d_in[19]; v3 = (const float*)d_in[20];
        Wg = (const float*)d_in[21]; ags = (const float*)d_in[22];
        agd = (const float*)d_in[23]; bg = (const float*)d_in[24];
        Wc1 = (const float*)d_in[25]; bc1 = (const float*)d_in[26];
        Wc2 = (const float*)d_in[27]; bc2 = (const float*)d_in[28];
    }

    const int* src = ei;
    const int* dst = ei + E;

    k_mega<<<NBLK, NTHR>>>(x, src, dst, batch, n, E, G,
                           W1, b1, g1, be1, m1, v1,
                           W2, b2, g2, be2, m2, v2,
                           W3, b3, g3, be3, m3, v3,
                           Wg, ags, agd, bg,
                           Wc1, bc1, Wc2, bc2,
                           (float*)d_out);
}

// round 11
// speedup vs baseline: 1.6571x; 1.0285x over previous
#include <cuda_runtime.h>
#include <cuda_bf16.h>
#include <math_constants.h>

#define NMAX 100000
#define GMAX 64
#define SLOTS 64
#define EPS 1e-5f
#define NEG_SLOPE 0.2f
#define NBLK 592          // 148 SMs x 4 blocks, all co-resident
#define NTHR 256

// ---------------- scratch (device globals) ----------------
__device__ __align__(16) unsigned g_B128[NMAX * 64];  // bf16x2, 128 cols/node
__device__ __align__(16) unsigned g_B64a[NMAX * 32];  // bf16x2, up to 64 cols/node
__device__ __align__(16) unsigned g_B64b[NMAX * 32];
__device__ float g_dinv[NMAX];
__device__ int   g_deg[NMAX];
__device__ int   g_cursor[NMAX];
__device__ int   g_perm[NMAX * SLOTS];
__device__ __align__(16) float g_as[NMAX * 4];
__device__ __align__(16) float g_ad[NMAX * 4];
__device__ float g_pool[GMAX * 32];
__device__ float g_cnt[GMAX];
__device__ unsigned g_gmaxu[4];
__device__ unsigned g_gen  = 0;
__device__ unsigned g_bcnt = 0;

// ---------------- grid-wide barrier (volatile-load polling) ----------------
__device__ __forceinline__ void gridbar() {
    __syncthreads();
    if (threadIdx.x == 0) {
        unsigned my = *(volatile unsigned*)&g_gen;
        __threadfence();
        if (atomicAdd(&g_bcnt, 1u) == NBLK - 1u) {
            atomicExch(&g_bcnt, 0u);
            __threadfence();
            atomicAdd(&g_gen, 1u);
        } else {
            while (*(volatile unsigned*)&g_gen == my) __nanosleep(64);
        }
        __threadfence();
    }
    __syncthreads();
}

__device__ __forceinline__ float lrelu(float x) { return x > 0.f ? x : NEG_SLOPE * x; }
__device__ __forceinline__ float2 bf2f(unsigned u) {
    return __bfloat1622float2(*reinterpret_cast<const __nv_bfloat162*>(&u));
}
__device__ __forceinline__ unsigned f2bf(float a, float b) {
    __nv_bfloat162 p = __floats2bfloat162_rn(a, b);
    return *reinterpret_cast<unsigned*>(&p);
}
__device__ __forceinline__ unsigned f2tf(float f) {
    unsigned u;
    asm("cvt.rna.tf32.f32 %0, %1;" : "=r"(u) : "f"(f));
    return u;
}
__device__ __forceinline__ unsigned fenc(float f) {
    int b = __float_as_int(f);
    return (b >= 0) ? ((unsigned)b | 0x80000000u) : (unsigned)(~b);
}
__device__ __forceinline__ float fdec(unsigned k) {
    return (k & 0x80000000u) ? __int_as_float((int)(k & 0x7FFFFFFFu))
                             : __int_as_float((int)~k);
}

__shared__ __align__(16) float smw[10240];   // 40KB stage scratch

// ---------------- tensor-core MMA m16n8k8 tf32 -> fp32 ----------------
__device__ __forceinline__ void mma1688(float c[4], unsigned a0, unsigned a1,
                                        unsigned a2, unsigned a3, unsigned b0, unsigned b1) {
    asm volatile(
        "mma.sync.aligned.m16n8k8.row.col.f32.tf32.tf32.f32 "
        "{%0,%1,%2,%3}, {%4,%5,%6,%7}, {%8,%9}, {%0,%1,%2,%3};"
        : "+f"(c[0]), "+f"(c[1]), "+f"(c[2]), "+f"(c[3])
        : "r"(a0), "r"(a1), "r"(a2), "r"(a3), "r"(b0), "r"(b1));
}

// ---------------- GEMM via tf32 MMA: A bf16 -> C bf16, opt bias+BN+relu, opt row-scale by dinv ----------------
template <int KIN, int KOUT, bool EPI, bool RSC>
__device__ void stage_mma(const unsigned* __restrict__ Ab, unsigned* __restrict__ Cb,
                          const float* __restrict__ W, int n, int lane, int gw, int GW,
                          const float* __restrict__ bias, const float* __restrict__ gam,
                          const float* __restrict__ bet, const float* __restrict__ mu,
                          const float* __restrict__ var) {
    constexpr int KS = KIN / 8;
    constexpr int NT = KOUT / 8;
    constexpr int JT = (NT >= 8) ? 8 : NT;
    constexpr int CHUNKS = NT / JT;
    constexpr int KIN2 = KIN / 2;
    constexpr int KOUT2 = KOUT / 2;

    uint2* bsm = reinterpret_cast<uint2*>(smw);
    for (int i = threadIdx.x; i < NT * KS * 32; i += NTHR) {
        int j = i / (KS * 32);
        int rem = i - j * (KS * 32);
        int s = rem >> 5;
        int l = rem & 31;
        int c_ = l & 3, nn = 8 * j + (l >> 2);
        int k0 = 8 * s + c_;
        unsigned v0 = f2tf(__ldg(W + k0 * KOUT + nn));
        unsigned v1 = f2tf(__ldg(W + (k0 + 4) * KOUT + nn));
        bsm[i] = make_uint2(v0, v1);
    }
    float* epiA = smw + 8192;
    float* epiB = smw + 8192 + KOUT;
    if constexpr (EPI) {
        for (int cix = threadIdx.x; cix < KOUT; cix += NTHR) {
            float Av = __ldg(gam + cix) * rsqrtf(__ldg(var + cix) + EPS);
            epiA[cix] = Av;
            epiB[cix] = __ldg(bet + cix) + (__ldg(bias + cix) - __ldg(mu + cix)) * Av;
        }
    }
    __syncthreads();

    int nrt = (n + 15) >> 4;
    int c = lane & 3, q = lane >> 2;
    int hw = c >> 1;
    bool hi = (c & 1);
    for (int T = gw; T < nrt * CHUNKS; T += GW) {
        int rt = (CHUNKS == 1) ? T : (T / CHUNKS);
        int ch = (CHUNKS == 1) ? 0 : (T - rt * CHUNKS);
        int r0 = rt * 16 + q;
        int r1 = r0 + 8;
        int rA = r0 < n ? r0 : n - 1;
        int rB = r1 < n ? r1 : n - 1;
        const unsigned* arow0 = Ab + (size_t)rA * KIN2;
        const unsigned* arow1 = Ab + (size_t)rB * KIN2;
        float acc[JT][4];
#pragma unroll
        for (int jj = 0; jj < JT; jj++) {
            acc[jj][0] = 0.f; acc[jj][1] = 0.f; acc[jj][2] = 0.f; acc[jj][3] = 0.f;
        }
#pragma unroll
        for (int s = 0; s < KS; s++) {
            unsigned wa0 = __ldg(arow0 + 4 * s + hw);
            unsigned wa1 = __ldg(arow0 + 4 * s + 2 + hw);
            unsigned wb0 = __ldg(arow1 + 4 * s + hw);
            unsigned wb1 = __ldg(arow1 + 4 * s + 2 + hw);
            unsigned a0 = hi ? (wa0 & 0xFFFF0000u) : (wa0 << 16);
            unsigned a2 = hi ? (wa1 & 0xFFFF0000u) : (wa1 << 16);
            unsigned a1 = hi ? (wb0 & 0xFFFF0000u) : (wb0 << 16);
            unsigned a3 = hi ? (wb1 & 0xFFFF0000u) : (wb1 << 16);
#pragma unroll
            for (int jj = 0; jj < JT; jj++) {
                uint2 bb = bsm[((ch * JT + jj) * KS + s) * 32 + lane];
                mma1688(acc[jj], a0, a1, a2, a3, bb.x, bb.y);
            }
        }
        float dr0 = 1.f, dr1 = 1.f;
        if constexpr (RSC) {
            dr0 = __ldg(g_dinv + rA);
            dr1 = __ldg(g_dinv + rB);
        }
#pragma unroll
        for (int jj = 0; jj < JT; jj++) {
            int col0 = 8 * (ch * JT + jj) + 2 * c;
            float x0 = acc[jj][0], x1 = acc[jj][1], x2 = acc[jj][2], x3 = acc[jj][3];
            if constexpr (EPI) {
                float A0 = epiA[col0], B0 = epiB[col0];
                float A1 = epiA[col0 + 1], B1 = epiB[col0 + 1];
                x0 = fmaxf(x0 * A0 + B0, 0.f); x1 = fmaxf(x1 * A1 + B1, 0.f);
                x2 = fmaxf(x2 * A0 + B0, 0.f); x3 = fmaxf(x3 * A1 + B1, 0.f);
            }
            if constexpr (RSC) {
                x0 *= dr0; x1 *= dr0; x2 *= dr1; x3 *= dr1;
            }
            int ci = col0 >> 1;
            if (r0 < n) Cb[(size_t)r0 * KOUT2 + ci] = f2bf(x0, x1);
            if (r1 < n) Cb[(size_t)r1 * KOUT2 + ci] = f2bf(x2, x3);
        }
    }
}

// ---------------- GCN agg (D=64), PRESCALED features: pure adds, dual-edge half-warps ----------------
// featb rows hold feat' = dinv*feat (bf16). out = [EPIL] relu((di*acc)*A + B) else bf16(di*acc).
template <bool EPIL>
__device__ void stage_agg64(const unsigned* __restrict__ featb, unsigned* __restrict__ outb, int n,
                            int lane, int gw, int GW,
                            const float* __restrict__ bias, const float* __restrict__ gam,
                            const float* __restrict__ bet, const float* __restrict__ mu,
                            const float* __restrict__ var) {
    const uint2* fb = reinterpret_cast<const uint2*>(featb);   // 16 uint2 per row
    uint2* ob = reinterpret_cast<uint2*>(outb);
    int h = lane >> 4;       // half id: edges h, h+2, h+4, ...
    int li = lane & 15;      // uint2 index within row -> dims [4li, 4li+3]
    float A0 = 1.f, A1 = 1.f, A2 = 1.f, A3 = 1.f, B0 = 0.f, B1 = 0.f, B2 = 0.f, B3 = 0.f;
    if constexpr (EPIL) {
        int d = 4 * li;
        A0 = __ldg(gam + d + 0) * rsqrtf(__ldg(var + d + 0) + EPS);
        B0 = __ldg(bet + d + 0) + (__ldg(bias + d + 0) - __ldg(mu + d + 0)) * A0;
        A1 = __ldg(gam + d + 1) * rsqrtf(__ldg(var + d + 1) + EPS);
        B1 = __ldg(bet + d + 1) + (__ldg(bias + d + 1) - __ldg(mu + d + 1)) * A1;
        A2 = __ldg(gam + d + 2) * rsqrtf(__ldg(var + d + 2) + EPS);
        B2 = __ldg(bet + d + 2) + (__ldg(bias + d + 2) - __ldg(mu + d + 2)) * A2;
        A3 = __ldg(gam + d + 3) * rsqrtf(__ldg(var + d + 3) + EPS);
        B3 = __ldg(bet + d + 3) + (__ldg(bias + d + 3) - __ldg(mu + d + 3)) * A3;
    }
    for (int w = gw; w < n; w += GW) {
        float di = g_dinv[w];
        int cnt = g_deg[w];
        const int* __restrict__ pl = g_perm + (size_t)w * SLOTS;
        float a0, a1, a2, a3;
        if (h == 0) {   // self loop contribution (feat'[w])
            uint2 v = __ldg(fb + (size_t)w * 16 + li);
            float2 p0 = bf2f(v.x), p1 = bf2f(v.y);
            a0 = p0.x; a1 = p0.y; a2 = p1.x; a3 = p1.y;
        } else {
            a0 = 0.f; a1 = 0.f; a2 = 0.f; a3 = 0.f;
        }
        int e = h;
        for (; e + 6 < cnt; e += 8) {
            int s0 = __ldg(pl + e), s1 = __ldg(pl + e + 2);
            int s2 = __ldg(pl + e + 4), s3 = __ldg(pl + e + 6);
            uint2 v0 = __ldg(fb + (size_t)s0 * 16 + li);
            uint2 v1 = __ldg(fb + (size_t)s1 * 16 + li);
            uint2 v2 = __ldg(fb + (size_t)s2 * 16 + li);
            uint2 v3 = __ldg(fb + (size_t)s3 * 16 + li);
            float2 p;
            p = bf2f(v0.x); a0 += p.x; a1 += p.y;  p = bf2f(v0.y); a2 += p.x; a3 += p.y;
            p = bf2f(v1.x); a0 += p.x; a1 += p.y;  p = bf2f(v1.y); a2 += p.x; a3 += p.y;
            p = bf2f(v2.x); a0 += p.x; a1 += p.y;  p = bf2f(v2.y); a2 += p.x; a3 += p.y;
            p = bf2f(v3.x); a0 += p.x; a1 += p.y;  p = bf2f(v3.y); a2 += p.x; a3 += p.y;
        }
        for (; e < cnt; e += 2) {
            int sn = __ldg(pl + e);
            uint2 v = __ldg(fb + (size_t)sn * 16 + li);
            float2 p0 = bf2f(v.x), p1 = bf2f(v.y);
            a0 += p0.x; a1 += p0.y; a2 += p1.x; a3 += p1.y;
        }
        __syncwarp();
        a0 += __shfl_down_sync(0xffffffffu, a0, 16);
        a1 += __shfl_down_sync(0xffffffffu, a1, 16);
        a2 += __shfl_down_sync(0xffffffffu, a2, 16);
        a3 += __shfl_down_sync(0xffffffffu, a3, 16);
        if (lane < 16) {
            float o0, o1, o2, o3;
            if constexpr (EPIL) {
                o0 = fmaxf(a0 * (di * A0) + B0, 0.f);
                o1 = fmaxf(a1 * (di * A1) + B1, 0.f);
                o2 = fmaxf(a2 * (di * A2) + B2, 0.f);
                o3 = fmaxf(a3 * (di * A3) + B3, 0.f);
            } else {
                o0 = a0 * di; o1 = a1 * di; o2 = a2 * di; o3 = a3 * di;
            }
            ob[(size_t)w * 16 + li] = make_uint2(f2bf(o0, o1), f2bf(o2, o3));
        }
    }
}

// ---------------- GCN agg (D=32), PRESCALED, two nodes per warp, bf16 out + BN epilogue ----------------
__device__ void stage_agg32_dual(const unsigned* __restrict__ featb, unsigned* __restrict__ outb, int n,
                                 int lane, int gw, int GW,
                                 const float* __restrict__ bias, const float* __restrict__ gam,
                                 const float* __restrict__ bet, const float* __restrict__ mu,
                                 const float* __restrict__ var) {
    int sub = lane >> 4;
    int li = lane & 15;
    int d0 = 2 * li, d1 = 2 * li + 1;
    float A0 = __ldg(gam + d0) * rsqrtf(__ldg(var + d0) + EPS);
    float B0 = __ldg(bet + d0) + (__ldg(bias + d0) - __ldg(mu + d0)) * A0;
    float A1 = __ldg(gam + d1) * rsqrtf(__ldg(var + d1) + EPS);
    float B1 = __ldg(bet + d1) + (__ldg(bias + d1) - __ldg(mu + d1)) * A1;

    for (int base = gw * 2; base < n; base += GW * 2) {
        int w = base + sub;
        bool valid = w < n;
        int wc = valid ? w : n - 1;
        float di = g_dinv[wc];
        int cnt = g_deg[wc];
        int cnto = __shfl_xor_sync(0xffffffffu, cnt, 16);
        int cmax = cnt > cnto ? cnt : cnto;
        const int* __restrict__ pl = g_perm + (size_t)wc * SLOTS;
        float ax, ay;
        {
            float2 v = bf2f(__ldg(featb + (size_t)wc * 16 + li));
            ax = v.x; ay = v.y;    // self term (prescaled)
        }
        int e = 0;
        for (; e + 4 <= cmax; e += 4) {
            int s[4]; float g[4]; unsigned r[4];
#pragma unroll
            for (int u = 0; u < 4; u++) {
                bool a = (e + u) < cnt;
                s[u] = a ? __ldg(pl + e + u) : wc;
                g[u] = a ? 1.f : 0.f;
            }
#pragma unroll
            for (int u = 0; u < 4; u++) r[u] = __ldg(featb + (size_t)s[u] * 16 + li);
#pragma unroll
            for (int u = 0; u < 4; u++) {
                float2 v = bf2f(r[u]);
                ax += g[u] * v.x; ay += g[u] * v.y;
            }
        }
        for (; e < cmax; e++) {
            bool a = e < cnt;
            int sn = a ? __ldg(pl + e) : wc;
            float g = a ? 1.f : 0.f;
            float2 v = bf2f(__ldg(featb + (size_t)sn * 16 + li));
            ax += g * v.x; ay += g * v.y;
        }
        ax = fmaxf(ax * (di * A0) + B0, 0.f);
        ay = fmaxf(ay * (di * A1) + B1, 0.f);
        if (valid) outb[(size_t)w * 16 + li] = f2bf(ax, ay);
    }
}

// ---------------- the megakernel ----------------
__global__ void __launch_bounds__(NTHR, 4)
k_mega(const float* __restrict__ x, const int* __restrict__ src, const int* __restrict__ dst,
       const int* __restrict__ batch, int n, int E, int G,
       const float* W1, const float* b1, const float* g1, const float* be1, const float* m1, const float* v1,
       const float* W2, const float* b2, const float* g2, const float* be2, const float* m2, const float* v2,
       const float* W3, const float* b3, const float* g3, const float* be3, const float* m3, const float* v3,
       const float* Wg, const float* ags, const float* agd, const float* bg,
       const float* Wc1, const float* bc1, const float* Wc2, const float* bc2,
       float* __restrict__ out) {
    int tid = threadIdx.x;
    int lane = tid & 31;
    int gt = blockIdx.x * NTHR + tid;
    int gw = gt >> 5;
    const int GT = NBLK * NTHR;
    const int GW = GT / 32;

    // S0: zero cursors/pool/cnt/gmax
    for (int i = gt; i < n; i += GT) g_cursor[i] = 0;
    if (gt < GMAX * 32) g_pool[gt] = 0.f;
    if (gt < GMAX) g_cnt[gt] = 0.f;
    if (gt < 4) g_gmaxu[gt] = 0u;
    gridbar();

    // S1: bucket scatter by dst
    for (int e = gt; e < E; e += GT) {
        int d = dst[e];
        int slot = atomicAdd(&g_cursor[d], 1);
        if (slot < SLOTS) g_perm[(size_t)d * SLOTS + slot] = src[e];
    }
    gridbar();

    // S2: finalize degree/dinv + convert x -> prescaled bf16 (both loops read only g_cursor)
    for (int i = gt; i < n; i += GT) {
        int c = g_cursor[i];
        if (c > SLOTS) c = SLOTS;
        g_deg[i] = c;
        g_dinv[i] = rsqrtf((float)(c + 1));
    }
    for (int i = gt; i < n * 32; i += GT) {
        int node = i >> 5;
        int c = g_cursor[node];
        if (c > SLOTS) c = SLOTS;
        float di = rsqrtf((float)(c + 1));
        g_B64a[i] = f2bf(di * __ldg(x + 2 * i), di * __ldg(x + 2 * i + 1));
    }
    gridbar();

    // S3: aggregate prescaled input (linearity), out = bf16(di*acc)
    stage_agg64<false>(g_B64a, g_B64b, n, lane, gw, GW, nullptr, nullptr, nullptr, nullptr, nullptr);
    gridbar();

    // S4: tf32 GEMM 64->128 + bias/BN/relu
    stage_mma<64, 128, true, false>(g_B64b, g_B128, W1, n, lane, gw, GW, b1, g1, be1, m1, v1);
    gridbar();

    // S5: tf32 GEMM 128->64, out prescaled by dinv
    stage_mma<128, 64, false, true>(g_B128, g_B64a, W2, n, lane, gw, GW, nullptr, nullptr, nullptr, nullptr, nullptr);
    gridbar();

    // S6: aggregate + bias/BN/relu (di folded into epilogue)
    stage_agg64<true>(g_B64a, g_B64b, n, lane, gw, GW, b2, g2, be2, m2, v2);
    gridbar();

    // S7: tf32 GEMM 64->32, out prescaled by dinv
    stage_mma<64, 32, false, true>(g_B64b, g_B64a, W3, n, lane, gw, GW, nullptr, nullptr, nullptr, nullptr, nullptr);
    gridbar();

    // S8: aggregate + bias/BN/relu (32-dim), two nodes/warp
    stage_agg32_dual(g_B64a, g_B64b, n, lane, gw, GW, b3, g3, be3, m3, v3);
    gridbar();

    // S9: tf32 GEMM 32->128 (GAT projection), unscaled bf16 out
    stage_mma<32, 128, false, false>(g_B64b, g_B128, Wg, n, lane, gw, GW, nullptr, nullptr, nullptr, nullptr, nullptr);
    gridbar();

    // S10: attention coefficients from bf16 hh + per-head global max
    {
        unsigned* gm = reinterpret_cast<unsigned*>(smw);
        if (tid < 4) gm[tid] = 0u;
        __syncthreads();
        const float4* ags4 = reinterpret_cast<const float4*>(ags);
        const float4* agd4 = reinterpret_cast<const float4*>(agd);
        float4 sg = __ldg(ags4 + lane);
        float4 dg = __ldg(agd4 + lane);
        const uint2* hb = reinterpret_cast<const uint2*>(g_B128);
        float smax = -CUDART_INF_F;
        for (int node = gw; node < n; node += GW) {
            uint2 w = __ldg(hb + (size_t)node * 32 + lane);
            float2 p0 = bf2f(w.x), p1 = bf2f(w.y);
            float s = p0.x * sg.x + p0.y * sg.y + p1.x * sg.z + p1.y * sg.w;
            float d = p0.x * dg.x + p0.y * dg.y + p1.x * dg.z + p1.y * dg.w;
#pragma unroll
            for (int off = 4; off; off >>= 1) {
                s += __shfl_xor_sync(0xffffffffu, s, off);
                d += __shfl_xor_sync(0xffffffffu, d, off);
            }
            if ((lane & 7) == 0) {
                int h = lane >> 3;
                g_as[node * 4 + h] = s;
                g_ad[node * 4 + h] = d;
            }
            smax = fmaxf(smax, s);
        }
        if ((lane & 7) == 0) atomicMax(&gm[lane >> 3], fenc(smax));
        __syncthreads();
        if (tid < 4) atomicMax(&g_gmaxu[tid], gm[tid]);
    }
    gridbar();

    // S11: GAT aggregation (bf16 gather, global-max softmax) + bias/relu + fused pool
    {
        const uint2* hb = reinterpret_cast<const uint2*>(g_B128);
        int myh = lane >> 3;
        float gmax = fdec(g_gmaxu[myh]);
        for (int nId = gw; nId < n; nId += GW) {
            const int* __restrict__ pl = g_perm + (size_t)nId * SLOTS;
            int cnt = g_deg[nId];
            float4 adn4 = __ldg(reinterpret_cast<const float4*>(g_ad) + nId);
            float adn = (myh == 0) ? adn4.x : (myh == 1) ? adn4.y : (myh == 2) ? adn4.z : adn4.w;
            float mx = lrelu(gmax + adn);

            float4 acc = make_float4(0.f, 0.f, 0.f, 0.f);
            float den = 0.f;
            int e = 0;
            for (; e + 4 <= cnt; e += 4) {
                int s0 = __ldg(pl + e + 0), s1 = __ldg(pl + e + 1);
                int s2 = __ldg(pl + e + 2), s3 = __ldg(pl + e + 3);
                uint2 r0 = __ldg(hb + (size_t)s0 * 32 + lane);
                uint2 r1 = __ldg(hb + (size_t)s1 * 32 + lane);
                uint2 r2 = __ldg(hb + (size_t)s2 * 32 + lane);
                uint2 r3 = __ldg(hb + (size_t)s3 * 32 + lane);
                float w0 = __expf(lrelu(__ldg(&g_as[s0 * 4 + myh]) + adn) - mx);
                float w1 = __expf(lrelu(__ldg(&g_as[s1 * 4 + myh]) + adn) - mx);
                float w2 = __expf(lrelu(__ldg(&g_as[s2 * 4 + myh]) + adn) - mx);
                float w3 = __expf(lrelu(__ldg(&g_as[s3 * 4 + myh]) + adn) - mx);
                den += (w0 + w1) + (w2 + w3);
                float2 a0 = bf2f(r0.x), b0 = bf2f(r0.y);
                float2 a1 = bf2f(r1.x), b1 = bf2f(r1.y);
                float2 a2 = bf2f(r2.x), b2 = bf2f(r2.y);
                float2 a3 = bf2f(r3.x), b3 = bf2f(r3.y);
                acc.x += w0 * a0.x + w1 * a1.x + w2 * a2.x + w3 * a3.x;
                acc.y += w0 * a0.y + w1 * a1.y + w2 * a2.y + w3 * a3.y;
                acc.z += w0 * b0.x + w1 * b1.x + w2 * b2.x + w3 * b3.x;
                acc.w += w0 * b0.y + w1 * b1.y + w2 * b2.y + w3 * b3.y;
            }
            for (; e <= cnt; e++) {
                int sn = (e < cnt) ? __ldg(pl + e) : nId;
                float w = __expf(lrelu(__ldg(&g_as[sn * 4 + myh]) + adn) - mx);
                den += w;
                uint2 r = __ldg(hb + (size_t)sn * 32 + lane);
                float2 a = bf2f(r.x), b = bf2f(r.y);
                acc.x += w * a.x; acc.y += w * a.y; acc.z += w * b.x; acc.w += w * b.y;
            }
            float inv = 1.f / den;
            acc.x *= inv; acc.y *= inv; acc.z *= inv; acc.w *= inv;
#pragma unroll
            for (int off = 8; off <= 16; off <<= 1) {
                acc.x += __shfl_xor_sync(0xffffffffu, acc.x, off);
                acc.y += __shfl_xor_sync(0xffffffffu, acc.y, off);
                acc.z += __shfl_xor_sync(0xffffffffu, acc.z, off);
                acc.w += __shfl_xor_sync(0xffffffffu, acc.w, off);
            }
            if (lane < 8) {
                float4 bgv = __ldg(reinterpret_cast<const float4*>(bg) + lane);
                int b = __ldg(batch + nId);
                float* p = &g_pool[b * 32 + lane * 4];
                atomicAdd(p + 0, fmaxf(acc.x * 0.25f + bgv.x, 0.f));
                atomicAdd(p + 1, fmaxf(acc.y * 0.25f + bgv.y, 0.f));
                atomicAdd(p + 2, fmaxf(acc.z * 0.25f + bgv.z, 0.f));
                atomicAdd(p + 3, fmaxf(acc.w * 0.25f + bgv.w, 0.f));
                if (lane == 0) atomicAdd(&g_cnt[b], 1.f);
            }
        }
    }
    gridbar();

    // S12: classifier head (block 0 only)
    if (blockIdx.x == 0) {
        float* pooled = smw;
        float* hid = smw + GMAX * 32;
        for (int t = tid; t < G * 32; t += NTHR) pooled[t] = g_pool[t] / fmaxf(g_cnt[t >> 5], 1.f);
        __syncthreads();
        for (int t = tid; t < G * 16; t += NTHR) {
            int g = t >> 4, j = t & 15;
            float s = __ldg(bc1 + j);
            for (int k = 0; k < 32; k++) s += pooled[g * 32 + k] * __ldg(Wc1 + k * 16 + j);
            hid[t] = fmaxf(s, 0.f);
        }
        __syncthreads();
        for (int t = tid; t < G * 5; t += NTHR) {
            int g = t / 5, c = t % 5;
            float s = __ldg(bc2 + c);
            for (int k = 0; k < 16; k++) s += hid[g * 16 + k] * __ldg(Wc2 + k * 5 + c);
            out[t] = s;
        }
    }
}

// ---------------- host ----------------
extern "C" void kernel_launch(void* const* d_in, const int* in_sizes, int n_in,
                              void* d_out, int out_size) {
    const float* x = (const float*)d_in[0];
    const int* ei = (const int*)d_in[1];
    const int* batch = (const int*)d_in[2];
    int n = in_sizes[0] / 64;
    int E = in_sizes[1] / 2;
    int G = out_size / 5;

    const float *W1, *b1, *W2, *b2, *W3, *b3;
    const float *g1, *be1, *m1, *v1, *g2, *be2, *m2, *v2, *g3, *be3, *m3, *v3;
    const float *Wg, *ags, *agd, *bg, *Wc1, *bc1, *Wc2, *bc2;

    if (in_sizes[5] == 128 * 64) {
        W1 = (const float*)d_in[3];  b1 = (const float*)d_in[4];
        W2 = (const float*)d_in[5];  b2 = (const float*)d_in[6];
        W3 = (const float*)d_in[7];  b3 = (const float*)d_in[8];
        g1 = (const float*)d_in[9];  be1 = (const float*)d_in[10];
        m1 = (const float*)d_in[11]; v1 = (const float*)d_in[12];
        g2 = (const float*)d_in[13]; be2 = (const float*)d_in[14];
        m2 = (const float*)d_in[15]; v2 = (const float*)d_in[16];
        g3 = (const float*)d_in[17]; be3 = (const float*)d_in[18];
        m3 = (const float*)d_in[19]; v3 = (const float*)d_in[20];
        Wg = (const float*)d_in[21]; ags = (const float*)d_in[22];
        agd = (const float*)d_in[23]; bg = (const float*)d_in[24];
        Wc1 = (const float*)d_in[25]; bc1 = (const float*)d_in[26];
        Wc2 = (const float*)d_in[27]; bc2 = (const float*)d_in[28];
    } else {
        W1 = (const float*)d_in[3];  b1 = (const float*)d_in[4];
        g1 = (const float*)d_in[5];  be1 = (const float*)d_in[6];
        m1 = (const float*)d_in[7];  v1 = (const float*)d_in[8];
        W2 = (const float*)d_in[9];  b2 = (const float*)d_in[10];
        g2 = (const float*)d_in[11]; be2 = (const float*)d_in[12];
        m2 = (const float*)d_in[13]; v2 = (const float*)d_in[14];
        W3 = (const float*)d_in[15]; b3 = (const float*)d_in[16];
        g3 = (const float*)d_in[17]; be3 = (const float*)d_in[18];
        m3 = (const float*)d_in[19]; v3 = (const float*)d_in[20];
        Wg = (const float*)d_in[21]; ags = (const float*)d_in[22];
        agd = (const float*)d_in[23]; bg = (const float*)d_in[24];
        Wc1 = (const float*)d_in[25]; bc1 = (const float*)d_in[26];
        Wc2 = (const float*)d_in[27]; bc2 = (const float*)d_in[28];
    }

    const int* src = ei;
    const int* dst = ei + E;

    k_mega<<<NBLK, NTHR>>>(x, src, dst, batch, n, E, G,
                           W1, b1, g1, be1, m1, v1,
                           W2, b2, g2, be2, m2, v2,
                           W3, b3, g3, be3, m3, v3,
                           Wg, ags, agd, bg,
                           Wc1, bc1, Wc2, bc2,
                           (float*)d_out);
}